// round 5
// baseline (speedup 1.0000x reference)
#include <cuda_runtime.h>
#include <cuda_bf16.h>

// Problem constants
#define Bn 4
#define Ln 8
#define Nn 4096
#define Mn 2048
#define Kn 32
#define Sn 8
#define Jn 3

// Staging buffers (device globals; no runtime allocation)
__device__ float g_anchors[Bn * Sn * Mn * 3];
__device__ float g_P[Bn * 8 * Nn * 64];
__device__ float g_A[Bn * Sn * Mn * 64];
__device__ int   g_idx[Bn * Sn * Jn * Mn * Kn];
__device__ float g_hmax[Bn * Sn * Jn * Mn * 128];        // [combo][m][r]
__device__ float g_WtT[Jn * 128 * 256];                  // Wt transposed [j][r][o]
// Ws1 hi/lo pre-packed in mma.m16n8k16 A-fragment layout:
// index = ((w*4 + ks)*32 + lane)*4 + q   (w: row-block of 16, ks: k-step of 16)
__device__ unsigned g_WsFragHi[8 * 4 * 32 * 4];
__device__ unsigned g_WsFragLo[8 * 4 * 32 * 4];

// ---------------------------------------------------------------------------
// K1: FPS. One block per (b,s), 1024 threads, 4 pts each. Packed-key argmax
// (dist bits << 32 | ~idx) -> single u64 max reduction; ONE barrier per iter
// (double-buffered warp keys, block reduce done redundantly by all warps).
// Winner coords re-read from gmem (L1 broadcast). No-FMA arithmetic.
// ---------------------------------------------------------------------------
__global__ void __launch_bounds__(1024) fps_kernel(const float* __restrict__ xyzs,
                                                   float* __restrict__ out_xyz) {
    int bs = blockIdx.x;
    const float* xyz = xyzs + (size_t)bs * Nn * 3;
    __shared__ unsigned long long skey[2][32];

    int t = threadIdx.x;
    int lane = t & 31, wid = t >> 5;

    float px[4], py[4], pz[4], pd[4];
#pragma unroll
    for (int i = 0; i < 4; i++) {
        int p = t + i * 1024;
        px[i] = xyz[3 * p]; py[i] = xyz[3 * p + 1]; pz[i] = xyz[3 * p + 2];
        pd[i] = 1e10f;
    }
    float cx = xyz[0], cy = xyz[1], cz = xyz[2];

    float* oanc = g_anchors + (size_t)bs * Mn * 3;
    float* oxyz = out_xyz + (size_t)bs * Mn * 3;

    for (int m = 0; m < Mn; m++) {
        if (t == 0) {
            oanc[3 * m] = cx; oanc[3 * m + 1] = cy; oanc[3 * m + 2] = cz;
            oxyz[3 * m] = cx; oxyz[3 * m + 1] = cy; oxyz[3 * m + 2] = cz;
        }
        unsigned long long key = 0;
#pragma unroll
        for (int i = 0; i < 4; i++) {
            float dx = __fsub_rn(px[i], cx);
            float dy = __fsub_rn(py[i], cy);
            float dz = __fsub_rn(pz[i], cz);
            float d = __fadd_rn(__fadd_rn(__fmul_rn(dx, dx), __fmul_rn(dy, dy)),
                                __fmul_rn(dz, dz));
            float nd = fminf(pd[i], d);
            pd[i] = nd;
            unsigned long long k =
                ((unsigned long long)__float_as_uint(nd) << 32) |
                (unsigned)(0xFFFFFFFFu - (unsigned)(t + i * 1024));
            key = (k > key) ? k : key;
        }
#pragma unroll
        for (int off = 16; off > 0; off >>= 1) {
            unsigned long long k2 = __shfl_xor_sync(0xffffffffu, key, off);
            key = (k2 > key) ? k2 : key;
        }
        if (lane == 0) skey[m & 1][wid] = key;
        __syncthreads();
        key = skey[m & 1][lane];
#pragma unroll
        for (int off = 16; off > 0; off >>= 1) {
            unsigned long long k2 = __shfl_xor_sync(0xffffffffu, key, off);
            key = (k2 > key) ? k2 : key;
        }
        int widx = (int)(0xFFFFFFFFu - (unsigned)key);
        cx = xyz[3 * widx]; cy = xyz[3 * widx + 1]; cz = xyz[3 * widx + 2];
    }
}

// ---------------------------------------------------------------------------
// K2a: P = Ws0[:,0:3]@xyz + Ws0[:,3:6]@feat per point
// ---------------------------------------------------------------------------
__global__ void __launch_bounds__(256) compute_P(const float* __restrict__ xyzs,
                                                 const float* __restrict__ feats,
                                                 const float* __restrict__ Ws0) {
    __shared__ float w[64 * 6];
    int t = threadIdx.x;
    for (int i = t; i < 64 * 6; i += 256) w[i] = Ws0[i];
    __syncthreads();

    int gp = blockIdx.x * 256 + t;
    int n = gp & (Nn - 1);
    int bf = gp >> 12;
    const float* p = xyzs + (size_t)gp * 3;
    float x = p[0], y = p[1], z = p[2];
    const float* f = feats + (size_t)bf * 3 * Nn + n;
    float f0 = f[0], f1 = f[Nn], f2 = f[2 * Nn];
    float4* o = (float4*)(g_P + (size_t)gp * 64);
#pragma unroll
    for (int oo = 0; oo < 64; oo += 4) {
        float4 r;
        const float* w0 = w + oo * 6;
        r.x = w0[0] * x + w0[1] * y + w0[2] * z + w0[3] * f0 + w0[4] * f1 + w0[5] * f2;
        r.y = w0[6] * x + w0[7] * y + w0[8] * z + w0[9] * f0 + w0[10] * f1 + w0[11] * f2;
        r.z = w0[12] * x + w0[13] * y + w0[14] * z + w0[15] * f0 + w0[16] * f1 + w0[17] * f2;
        r.w = w0[18] * x + w0[19] * y + w0[20] * z + w0[21] * f0 + w0[22] * f1 + w0[23] * f2;
        o[oo >> 2] = r;
    }
}

// ---------------------------------------------------------------------------
// K2b: A = Ws0[:,0:3] @ anchor
// ---------------------------------------------------------------------------
__global__ void __launch_bounds__(256) compute_A(const float* __restrict__ Ws0) {
    __shared__ float w[64 * 3];
    int t = threadIdx.x;
    for (int i = t; i < 64 * 3; i += 256) {
        int o = i / 3, c = i % 3;
        w[i] = Ws0[o * 6 + c];
    }
    __syncthreads();
    int ga = blockIdx.x * 256 + t;
    const float* a = g_anchors + (size_t)ga * 3;
    float x = a[0], y = a[1], z = a[2];
    float4* o = (float4*)(g_A + (size_t)ga * 64);
#pragma unroll
    for (int oo = 0; oo < 64; oo += 4) {
        float4 r;
        const float* w0 = w + oo * 3;
        r.x = w0[0] * x + w0[1] * y + w0[2] * z;
        r.y = w0[3] * x + w0[4] * y + w0[5] * z;
        r.z = w0[6] * x + w0[7] * y + w0[8] * z;
        r.w = w0[9] * x + w0[10] * y + w0[11] * z;
        o[oo >> 2] = r;
    }
}

// ---------------------------------------------------------------------------
// K2c: transpose Wt -> WtT; pack Ws1 hi/lo into mma A-fragment layout.
// Fragment (w, ks, lane, q): row = w*16 + (lane>>2) + (q&1)*8,
//                            k   = ks*16 + (lane&3)*2 + ((q>>1)&1)*8; pair (k, k+1).
// ---------------------------------------------------------------------------
__global__ void __launch_bounds__(256) transpose_weights(const float* __restrict__ Wt,
                                                         const float* __restrict__ Ws1) {
    int t = blockIdx.x * 256 + threadIdx.x;
    if (t < Jn * 256 * 128) {
        int j = t / (256 * 128);
        int rem = t % (256 * 128);
        int o = rem / 128, r = rem % 128;
        g_WtT[(j * 128 + r) * 256 + o] = Wt[t];
    }
    if (t < 8 * 4 * 32 * 4) {
        int q = t & 3, lane = (t >> 2) & 31, ks = (t >> 7) & 3, w = t >> 9;
        int row = w * 16 + (lane >> 2) + (q & 1) * 8;
        int k = ks * 16 + (lane & 3) * 2 + ((q >> 1) & 1) * 8;
        float e0 = Ws1[row * 64 + k];
        float e1 = Ws1[row * 64 + k + 1];
        __nv_bfloat16 h0 = __float2bfloat16_rn(e0);
        __nv_bfloat16 h1 = __float2bfloat16_rn(e1);
        __nv_bfloat16 l0 = __float2bfloat16_rn(e0 - __bfloat162float(h0));
        __nv_bfloat16 l1 = __float2bfloat16_rn(e1 - __bfloat162float(h1));
        unsigned uh0 = *(unsigned short*)&h0, uh1 = *(unsigned short*)&h1;
        unsigned ul0 = *(unsigned short*)&l0, ul1 = *(unsigned short*)&l1;
        g_WsFragHi[t] = (uh1 << 16) | uh0;
        g_WsFragLo[t] = (ul1 << 16) | ul0;
    }
}

// ---------------------------------------------------------------------------
// K3: ball query (unchanged)
// ---------------------------------------------------------------------------
__global__ void __launch_bounds__(256) ball_query_kernel(const float* __restrict__ xyzs) {
    int combo = blockIdx.y;
    int j = combo % 3;
    int bs = combo / 3;
    int b = bs >> 3, s = bs & 7;
    int g = s - 1 + j;
    g = g < 0 ? 0 : (g > 7 ? 7 : g);
    int wid = threadIdx.x >> 5, lane = threadIdx.x & 31;
    int m = blockIdx.x * 8 + wid;

    const float* pts = xyzs + (size_t)(b * 8 + g) * Nn * 3;
    const float* anc = g_anchors + ((size_t)bs * Mn + m) * 3;
    float ax = anc[0], ay = anc[1], az = anc[2];
    int* out = g_idx + ((size_t)combo * Mn + m) * Kn;

    int found = 0, first = -1;
    unsigned lt = (1u << lane) - 1u;
    for (int base = 0; base < Nn && found < Kn; base += 32) {
        int n = base + lane;
        const float* pp = pts + 3 * n;
        float dx = __fsub_rn(pp[0], ax);
        float dy = __fsub_rn(pp[1], ay);
        float dz = __fsub_rn(pp[2], az);
        float d2 = __fadd_rn(__fadd_rn(__fmul_rn(dx, dx), __fmul_rn(dy, dy)),
                             __fmul_rn(dz, dz));
        bool pred = d2 < 0.25f;
        unsigned msk = __ballot_sync(0xffffffffu, pred);
        if (first < 0 && msk) first = base + (__ffs(msk) - 1);
        int pos = found + __popc(msk & lt);
        if (pred && pos < Kn) out[pos] = n;
        found += __popc(msk);
    }
    if (found < Kn) {
        int pad = first < 0 ? 0 : first;
        for (int p = found + lane; p < Kn; p += 32) out[p] = pad;
    }
}

// ---------------------------------------------------------------------------
// K4: layer-1 GEMM on tensor cores (bf16 hi/lo, 3 products), fused h0 + max
// pool. Tile: 128 rows x 128 cols (4 anchors), K=64. A fragments LDG'd from
// pre-packed gmem (L1-resident) — no W smem. B hi/lo in smem (32KB), XOR-16B
// swizzle. Per n-tile pair: 4 ldsm4 -> 12 mmas over 4 independent acc chains.
// ---------------------------------------------------------------------------
__device__ __forceinline__ void mma_bf16(float c[4], const unsigned a[4],
                                         unsigned b0, unsigned b1) {
    asm volatile(
        "mma.sync.aligned.m16n8k16.row.col.f32.bf16.bf16.f32 "
        "{%0,%1,%2,%3}, {%4,%5,%6,%7}, {%8,%9}, {%0,%1,%2,%3};"
        : "+f"(c[0]), "+f"(c[1]), "+f"(c[2]), "+f"(c[3])
        : "r"(a[0]), "r"(a[1]), "r"(a[2]), "r"(a[3]), "r"(b0), "r"(b1));
}

__device__ __forceinline__ void ldsm4(unsigned r[4], unsigned saddr) {
    asm volatile(
        "ldmatrix.sync.aligned.m8n8.x4.shared.b16 {%0,%1,%2,%3}, [%4];"
        : "=r"(r[0]), "=r"(r[1]), "=r"(r[2]), "=r"(r[3])
        : "r"(saddr));
}

__global__ void __launch_bounds__(256, 2) mlp_kernel() {
    __shared__ __align__(16) __nv_bfloat16 Bhi[128 * 64];  // 16KB  [col][k] swizzled
    __shared__ __align__(16) __nv_bfloat16 Blo[128 * 64];  // 16KB

    int t = threadIdx.x;
    int lane = t & 31, w = t >> 5;
    int combo = blockIdx.y;
    int j = combo % 3;
    int bs = combo / 3;
    int b = bs >> 3, s = bs & 7;
    int g = s - 1 + j;
    g = g < 0 ? 0 : (g > 7 ? 7 : g);

    // --- produce H hi/lo: thread owns (col, half of k) ---
    {
        int col = t & 127;
        int kh = t >> 7;  // 0..1 -> k range [kh*32, kh*32+32)
        int gcol = blockIdx.x * 128 + col;
        int m = gcol >> 5;
        int knb = gcol & 31;
        int n = g_idx[((size_t)combo * Mn + m) * Kn + knb];
        const float4* Prow = (const float4*)(g_P + ((size_t)(b * 8 + g) * Nn + n) * 64);
        const float4* Arow = (const float4*)(g_A + ((size_t)bs * Mn + m) * 64);
        char* bh = (char*)Bhi;
        char* bl = (char*)Blo;
#pragma unroll
        for (int q = 0; q < 8; q++) {
            float4 p4 = Prow[kh * 8 + q];
            float4 a4 = Arow[kh * 8 + q];
            float h0 = fmaxf(p4.x - a4.x, 0.f);
            float h1 = fmaxf(p4.y - a4.y, 0.f);
            float h2 = fmaxf(p4.z - a4.z, 0.f);
            float h3 = fmaxf(p4.w - a4.w, 0.f);
            __nv_bfloat162 hiA, hiB, loA, loB;
            hiA.x = __float2bfloat16_rn(h0); hiA.y = __float2bfloat16_rn(h1);
            hiB.x = __float2bfloat16_rn(h2); hiB.y = __float2bfloat16_rn(h3);
            loA.x = __float2bfloat16_rn(h0 - __bfloat162float(hiA.x));
            loA.y = __float2bfloat16_rn(h1 - __bfloat162float(hiA.y));
            loB.x = __float2bfloat16_rn(h2 - __bfloat162float(hiB.x));
            loB.y = __float2bfloat16_rn(h3 - __bfloat162float(hiB.y));
            int k0 = kh * 32 + q * 4;
            int chunk = k0 >> 3;
            int off = col * 128 + ((chunk ^ (col & 7)) << 4) + ((k0 & 7) << 1);
            uint2 vh, vl;
            vh.x = *(unsigned*)&hiA; vh.y = *(unsigned*)&hiB;
            vl.x = *(unsigned*)&loA; vl.y = *(unsigned*)&loB;
            *(uint2*)(bh + off) = vh;
            *(uint2*)(bl + off) = vl;
        }
    }
    __syncthreads();

    unsigned sBhi = (unsigned)__cvta_generic_to_shared(Bhi);
    unsigned sBlo = (unsigned)__cvta_generic_to_shared(Blo);

    float acc[16][4];
#pragma unroll
    for (int nt = 0; nt < 16; nt++)
#pragma unroll
        for (int i = 0; i < 4; i++) acc[nt][i] = 0.f;

    int brow_base = (lane & 7) + ((lane & 16) >> 1);
    int bksel = (lane >> 3) & 1;
    const uint4* fragHi = (const uint4*)g_WsFragHi;
    const uint4* fragLo = (const uint4*)g_WsFragLo;

#pragma unroll
    for (int ks = 0; ks < 4; ks++) {
        // A fragments from gmem (L1-hot, coalesced 16B/lane)
        uint4 fh = fragHi[(w * 4 + ks) * 32 + lane];
        uint4 fl = fragLo[(w * 4 + ks) * 32 + lane];
        unsigned ahi[4] = {fh.x, fh.y, fh.z, fh.w};
        unsigned alo[4] = {fl.x, fl.y, fl.z, fl.w};
        int chunk = ks * 2 + bksel;
#pragma unroll
        for (int pp = 0; pp < 4; pp++) {
            int p0 = 2 * pp, p1 = 2 * pp + 1;
            int r0 = p0 * 16 + brow_base;
            int r1 = p1 * 16 + brow_base;
            unsigned off0 = r0 * 128 + ((chunk ^ (r0 & 7)) << 4);
            unsigned off1 = r1 * 128 + ((chunk ^ (r1 & 7)) << 4);
            unsigned h0[4], h1[4], l0[4], l1[4];
            ldsm4(h0, sBhi + off0);
            ldsm4(h1, sBhi + off1);
            ldsm4(l0, sBlo + off0);
            ldsm4(l1, sBlo + off1);
            // 12 mmas round-robin over 4 independent accumulators
            mma_bf16(acc[2 * p0],     ahi, h0[0], h0[1]);
            mma_bf16(acc[2 * p0 + 1], ahi, h0[2], h0[3]);
            mma_bf16(acc[2 * p1],     ahi, h1[0], h1[1]);
            mma_bf16(acc[2 * p1 + 1], ahi, h1[2], h1[3]);
            mma_bf16(acc[2 * p0],     alo, h0[0], h0[1]);
            mma_bf16(acc[2 * p0 + 1], alo, h0[2], h0[3]);
            mma_bf16(acc[2 * p1],     alo, h1[0], h1[1]);
            mma_bf16(acc[2 * p1 + 1], alo, h1[2], h1[3]);
            mma_bf16(acc[2 * p0],     ahi, l0[0], l0[1]);
            mma_bf16(acc[2 * p0 + 1], ahi, l0[2], l0[3]);
            mma_bf16(acc[2 * p1],     ahi, l1[0], l1[1]);
            mma_bf16(acc[2 * p1 + 1], ahi, l1[2], l1[3]);
        }
    }
    __syncthreads();

    // --- epilogue: per-anchor max over 32 cols via quad shuffles ---
    float* hm = (float*)Bhi;  // scratch [4][128]
#pragma unroll
    for (int a = 0; a < 4; a++) {
        float m0 = -1e30f, m1 = -1e30f;
#pragma unroll
        for (int nt = a * 4; nt < a * 4 + 4; nt++) {
            m0 = fmaxf(m0, fmaxf(acc[nt][0], acc[nt][1]));
            m1 = fmaxf(m1, fmaxf(acc[nt][2], acc[nt][3]));
        }
        m0 = fmaxf(m0, __shfl_xor_sync(0xffffffffu, m0, 1));
        m0 = fmaxf(m0, __shfl_xor_sync(0xffffffffu, m0, 2));
        m1 = fmaxf(m1, __shfl_xor_sync(0xffffffffu, m1, 1));
        m1 = fmaxf(m1, __shfl_xor_sync(0xffffffffu, m1, 2));
        if ((lane & 3) == 0) {
            int grp = lane >> 2;
            hm[a * 128 + w * 16 + grp] = fmaxf(m0, 0.f);
            hm[a * 128 + w * 16 + grp + 8] = fmaxf(m1, 0.f);
        }
    }
    __syncthreads();

    int mbase = blockIdx.x * 4;
    for (int i = t; i < 512; i += 256) {
        int a = i >> 7, r = i & 127;
        g_hmax[((size_t)combo * Mn + mbase + a) * 128 + r] = hm[a * 128 + r];
    }
}

// ---------------------------------------------------------------------------
// K5: out = sum_j relu(Wt[j] @ hmax[j]) (unchanged)
// ---------------------------------------------------------------------------
__global__ void __launch_bounds__(256) wt_kernel(float* __restrict__ outf) {
    __shared__ float hsh[32 * 128];
    int t = threadIdx.x;
    int bs = blockIdx.y;
    int mbase = blockIdx.x * 32;

    float tot[32];
#pragma unroll
    for (int i = 0; i < 32; i++) tot[i] = 0.f;

    for (int j = 0; j < 3; j++) {
        const float* hb = g_hmax + ((size_t)(bs * 3 + j) * Mn + mbase) * 128;
        for (int i = t; i < 32 * 128; i += 256) hsh[i] = hb[i];
        __syncthreads();

        float acc[32];
#pragma unroll
        for (int i = 0; i < 32; i++) acc[i] = 0.f;

        const float* wtb = g_WtT + (size_t)j * 128 * 256 + t;
        for (int r = 0; r < 128; r += 4) {
            float w0 = wtb[(r + 0) * 256];
            float w1 = wtb[(r + 1) * 256];
            float w2 = wtb[(r + 2) * 256];
            float w3 = wtb[(r + 3) * 256];
#pragma unroll
            for (int mm = 0; mm < 32; mm++) {
                float4 h = *(const float4*)&hsh[mm * 128 + r];
                acc[mm] += w0 * h.x + w1 * h.y + w2 * h.z + w3 * h.w;
            }
        }
#pragma unroll
        for (int i = 0; i < 32; i++) tot[i] += fmaxf(acc[i], 0.f);
        __syncthreads();
    }

    float4* o = (float4*)(outf + ((size_t)bs * 256 + t) * Mn + mbase);
#pragma unroll
    for (int q = 0; q < 8; q++) {
        float4 r;
        r.x = tot[4 * q + 0];
        r.y = tot[4 * q + 1];
        r.z = tot[4 * q + 2];
        r.w = tot[4 * q + 3];
        o[q] = r;
    }
}

// ---------------------------------------------------------------------------
extern "C" void kernel_launch(void* const* d_in, const int* in_sizes, int n_in,
                              void* d_out, int out_size) {
    const float* xyzs = (const float*)d_in[0];
    const float* feats = (const float*)d_in[1];
    const float* Ws0 = (const float*)d_in[2];
    const float* Ws1 = (const float*)d_in[3];
    const float* Wt = (const float*)d_in[4];
    float* out = (float*)d_out;

    const int XYZ_TOTAL = Bn * Sn * Mn * 3;  // 196608

    fps_kernel<<<Bn * Sn, 1024>>>(xyzs, out);
    compute_P<<<Bn * 8 * Nn / 256, 256>>>(xyzs, feats, Ws0);
    transpose_weights<<<(Jn * 256 * 128 + 255) / 256, 256>>>(Wt, Ws1);
    ball_query_kernel<<<dim3(Mn / 8, Bn * Sn * Jn), 256>>>(xyzs);  // slot 4 (profiled)
    compute_A<<<Bn * Sn * Mn / 256, 256>>>(Ws0);
    mlp_kernel<<<dim3(Mn * Kn / 128, Bn * Sn * Jn), 256>>>();
    wt_kernel<<<dim3(Mn / 32, Bn * Sn), 256>>>(out + XYZ_TOTAL);
}

// round 6
// speedup vs baseline: 1.3108x; 1.3108x over previous
#include <cuda_runtime.h>
#include <cuda_bf16.h>

// Problem constants
#define Bn 4
#define Ln 8
#define Nn 4096
#define Mn 2048
#define Kn 32
#define Sn 8
#define Jn 3

// Staging buffers (device globals; no runtime allocation)
__device__ float g_anchors[Bn * Sn * Mn * 3];
__device__ float g_P[Bn * 8 * Nn * 64];
__device__ float g_A[Bn * Sn * Mn * 64];
__device__ int   g_idx[Bn * Sn * Jn * Mn * Kn];
__device__ float g_hmax[Bn * Sn * Jn * Mn * 128];        // [combo][m][r]
__device__ float g_WtT[Jn * 128 * 256];                  // Wt transposed [j][r][o]
__device__ __nv_bfloat16 g_Ws1hi[128 * 64];              // Ws1 hi, [r][k]
__device__ __nv_bfloat16 g_Ws1lo[128 * 64];              // Ws1 lo, [r][k]

// ---------------------------------------------------------------------------
// K1: FPS (R4 version — known good). One block per (b,s), 1024 threads,
// coords carried through argmax reduction, 2 barriers/iter. No-FMA math.
// ---------------------------------------------------------------------------
__global__ void __launch_bounds__(1024) fps_kernel(const float* __restrict__ xyzs,
                                                   float* __restrict__ out_xyz) {
    int bs = blockIdx.x;
    const float* xyz = xyzs + (size_t)bs * Nn * 3;
    __shared__ float rv[32], rx[32], ry[32], rz[32];
    __shared__ int ri[32];
    __shared__ float scx, scy, scz;

    int t = threadIdx.x;
    int lane = t & 31, wid = t >> 5;

    float px[4], py[4], pz[4], pd[4];
#pragma unroll
    for (int i = 0; i < 4; i++) {
        int p = t + i * 1024;
        px[i] = xyz[3 * p]; py[i] = xyz[3 * p + 1]; pz[i] = xyz[3 * p + 2];
        pd[i] = 1e10f;
    }
    if (t == 0) { scx = px[0]; scy = py[0]; scz = pz[0]; }
    __syncthreads();

    float* oanc = g_anchors + (size_t)bs * Mn * 3;
    float* oxyz = out_xyz + (size_t)bs * Mn * 3;

    for (int m = 0; m < Mn; m++) {
        float cx = scx, cy = scy, cz = scz;
        if (t == 0) {
            oanc[3 * m] = cx; oanc[3 * m + 1] = cy; oanc[3 * m + 2] = cz;
            oxyz[3 * m] = cx; oxyz[3 * m + 1] = cy; oxyz[3 * m + 2] = cz;
        }
        float best = -1.0f, bx = 0.f, by = 0.f, bz = 0.f;
        int bi = 0;
#pragma unroll
        for (int i = 0; i < 4; i++) {
            float dx = __fsub_rn(px[i], cx);
            float dy = __fsub_rn(py[i], cy);
            float dz = __fsub_rn(pz[i], cz);
            float d = __fadd_rn(__fadd_rn(__fmul_rn(dx, dx), __fmul_rn(dy, dy)),
                                __fmul_rn(dz, dz));
            float nd = fminf(pd[i], d);
            pd[i] = nd;
            if (nd > best) { best = nd; bi = t + i * 1024; bx = px[i]; by = py[i]; bz = pz[i]; }
        }
#pragma unroll
        for (int off = 16; off > 0; off >>= 1) {
            float v = __shfl_xor_sync(0xffffffffu, best, off);
            int j2 = __shfl_xor_sync(0xffffffffu, bi, off);
            float x2 = __shfl_xor_sync(0xffffffffu, bx, off);
            float y2 = __shfl_xor_sync(0xffffffffu, by, off);
            float z2 = __shfl_xor_sync(0xffffffffu, bz, off);
            if (v > best || (v == best && j2 < bi)) { best = v; bi = j2; bx = x2; by = y2; bz = z2; }
        }
        if (lane == 0) { rv[wid] = best; ri[wid] = bi; rx[wid] = bx; ry[wid] = by; rz[wid] = bz; }
        __syncthreads();
        if (wid == 0) {
            best = rv[lane]; bi = ri[lane]; bx = rx[lane]; by = ry[lane]; bz = rz[lane];
#pragma unroll
            for (int off = 16; off > 0; off >>= 1) {
                float v = __shfl_xor_sync(0xffffffffu, best, off);
                int j2 = __shfl_xor_sync(0xffffffffu, bi, off);
                float x2 = __shfl_xor_sync(0xffffffffu, bx, off);
                float y2 = __shfl_xor_sync(0xffffffffu, by, off);
                float z2 = __shfl_xor_sync(0xffffffffu, bz, off);
                if (v > best || (v == best && j2 < bi)) { best = v; bi = j2; bx = x2; by = y2; bz = z2; }
            }
            if (lane == 0) { scx = bx; scy = by; scz = bz; }
        }
        __syncthreads();
    }
}

// ---------------------------------------------------------------------------
// K2: merged P + A + weight prep.
//   blocks [0,512):    P[b][f][n][64] = Ws0[:,0:3]@xyz + Ws0[:,3:6]@feat
//   blocks [512,768):  A[ga][64] = Ws0[:,0:3]@anchor, plus a slice of
//                      WtT transpose and Ws1 hi/lo split.
// ---------------------------------------------------------------------------
__global__ void __launch_bounds__(256) compute_PAW(const float* __restrict__ xyzs,
                                                   const float* __restrict__ feats,
                                                   const float* __restrict__ Ws0,
                                                   const float* __restrict__ Ws1,
                                                   const float* __restrict__ Wt) {
    int t = threadIdx.x;
    if (blockIdx.x < 512) {
        __shared__ float w[64 * 6];
        for (int i = t; i < 64 * 6; i += 256) w[i] = Ws0[i];
        __syncthreads();

        int gp = blockIdx.x * 256 + t;
        int n = gp & (Nn - 1);
        int bf = gp >> 12;
        const float* p = xyzs + (size_t)gp * 3;
        float x = p[0], y = p[1], z = p[2];
        const float* f = feats + (size_t)bf * 3 * Nn + n;
        float f0 = f[0], f1 = f[Nn], f2 = f[2 * Nn];
        float4* o = (float4*)(g_P + (size_t)gp * 64);
#pragma unroll
        for (int oo = 0; oo < 64; oo += 4) {
            float4 r;
            const float* w0 = w + oo * 6;
            r.x = w0[0] * x + w0[1] * y + w0[2] * z + w0[3] * f0 + w0[4] * f1 + w0[5] * f2;
            r.y = w0[6] * x + w0[7] * y + w0[8] * z + w0[9] * f0 + w0[10] * f1 + w0[11] * f2;
            r.z = w0[12] * x + w0[13] * y + w0[14] * z + w0[15] * f0 + w0[16] * f1 + w0[17] * f2;
            r.w = w0[18] * x + w0[19] * y + w0[20] * z + w0[21] * f0 + w0[22] * f1 + w0[23] * f2;
            o[oo >> 2] = r;
        }
    } else {
        __shared__ float w[64 * 3];
        for (int i = t; i < 64 * 3; i += 256) {
            int o = i / 3, c = i % 3;
            w[i] = Ws0[o * 6 + c];
        }
        __syncthreads();
        int ga = (blockIdx.x - 512) * 256 + t;  // 0..65535
        const float* a = g_anchors + (size_t)ga * 3;
        float x = a[0], y = a[1], z = a[2];
        float4* o = (float4*)(g_A + (size_t)ga * 64);
#pragma unroll
        for (int oo = 0; oo < 64; oo += 4) {
            float4 r;
            const float* w0 = w + oo * 3;
            r.x = w0[0] * x + w0[1] * y + w0[2] * z;
            r.y = w0[3] * x + w0[4] * y + w0[5] * z;
            r.z = w0[6] * x + w0[7] * y + w0[8] * z;
            r.w = w0[9] * x + w0[10] * y + w0[11] * z;
            o[oo >> 2] = r;
        }
        // weight prep, spread across these 65536 threads
        for (int i = ga; i < Jn * 256 * 128; i += 65536) {
            int j = i / (256 * 128);
            int rem = i % (256 * 128);
            int oo = rem / 128, r = rem % 128;
            g_WtT[(j * 128 + r) * 256 + oo] = Wt[i];
        }
        if (ga < 128 * 64) {
            float ww = Ws1[ga];
            __nv_bfloat16 hi = __float2bfloat16_rn(ww);
            __nv_bfloat16 lo = __float2bfloat16_rn(ww - __bfloat162float(hi));
            g_Ws1hi[ga] = hi;
            g_Ws1lo[ga] = lo;
        }
    }
}

// ---------------------------------------------------------------------------
// K3: ball query (unchanged)
// ---------------------------------------------------------------------------
__global__ void __launch_bounds__(256) ball_query_kernel(const float* __restrict__ xyzs) {
    int combo = blockIdx.y;
    int j = combo % 3;
    int bs = combo / 3;
    int b = bs >> 3, s = bs & 7;
    int g = s - 1 + j;
    g = g < 0 ? 0 : (g > 7 ? 7 : g);
    int wid = threadIdx.x >> 5, lane = threadIdx.x & 31;
    int m = blockIdx.x * 8 + wid;

    const float* pts = xyzs + (size_t)(b * 8 + g) * Nn * 3;
    const float* anc = g_anchors + ((size_t)bs * Mn + m) * 3;
    float ax = anc[0], ay = anc[1], az = anc[2];
    int* out = g_idx + ((size_t)combo * Mn + m) * Kn;

    int found = 0, first = -1;
    unsigned lt = (1u << lane) - 1u;
    for (int base = 0; base < Nn && found < Kn; base += 32) {
        int n = base + lane;
        const float* pp = pts + 3 * n;
        float dx = __fsub_rn(pp[0], ax);
        float dy = __fsub_rn(pp[1], ay);
        float dz = __fsub_rn(pp[2], az);
        float d2 = __fadd_rn(__fadd_rn(__fmul_rn(dx, dx), __fmul_rn(dy, dy)),
                             __fmul_rn(dz, dz));
        bool pred = d2 < 0.25f;
        unsigned msk = __ballot_sync(0xffffffffu, pred);
        if (first < 0 && msk) first = base + (__ffs(msk) - 1);
        int pos = found + __popc(msk & lt);
        if (pred && pos < Kn) out[pos] = n;
        found += __popc(msk);
    }
    if (found < Kn) {
        int pad = first < 0 ? 0 : first;
        for (int p = found + lane; p < Kn; p += 32) out[p] = pad;
    }
}

// ---------------------------------------------------------------------------
// K4: layer-1 GEMM on tensor cores (bf16 hi/lo split, 3 mma products), fused
// h0 generation + 32-way max pool. R4 structure (known good): 128 rows x
// 64 cols per rep, K=64, W in smem, A-frags hoisted; NOW 2 column-tile reps
// per block reusing W smem + A frags. Static smem 48KB.
// ---------------------------------------------------------------------------
__device__ __forceinline__ void mma_bf16(float c[4], const unsigned a[4],
                                         unsigned b0, unsigned b1) {
    asm volatile(
        "mma.sync.aligned.m16n8k16.row.col.f32.bf16.bf16.f32 "
        "{%0,%1,%2,%3}, {%4,%5,%6,%7}, {%8,%9}, {%0,%1,%2,%3};"
        : "+f"(c[0]), "+f"(c[1]), "+f"(c[2]), "+f"(c[3])
        : "r"(a[0]), "r"(a[1]), "r"(a[2]), "r"(a[3]), "r"(b0), "r"(b1));
}

__device__ __forceinline__ void ldsm4(unsigned r[4], unsigned saddr) {
    asm volatile(
        "ldmatrix.sync.aligned.m8n8.x4.shared.b16 {%0,%1,%2,%3}, [%4];"
        : "=r"(r[0]), "=r"(r[1]), "=r"(r[2]), "=r"(r[3])
        : "r"(saddr));
}

__global__ void __launch_bounds__(256) mlp_kernel() {
    __shared__ __align__(16) __nv_bfloat16 Ahi[128 * 64];  // 16KB  W hi [r][k] swizzled
    __shared__ __align__(16) __nv_bfloat16 Alo[128 * 64];  // 16KB  W lo
    __shared__ __align__(16) __nv_bfloat16 Bhi[64 * 64];   //  8KB  H hi [col][k] swizzled
    __shared__ __align__(16) __nv_bfloat16 Blo[64 * 64];   //  8KB  H lo

    int t = threadIdx.x;
    int lane = t & 31, w = t >> 5;
    int combo = blockIdx.y;
    int j = combo % 3;
    int bs = combo / 3;
    int b = bs >> 3, s = bs & 7;
    int g = s - 1 + j;
    g = g < 0 ? 0 : (g > 7 ? 7 : g);

    // --- load W hi/lo into smem with 16B-chunk XOR swizzle ---
    {
        const uint4* gh = (const uint4*)g_Ws1hi;  // 1024 x 16B
        const uint4* gl = (const uint4*)g_Ws1lo;
        uint4* sh = (uint4*)Ahi;
        uint4* sl = (uint4*)Alo;
        for (int i = t; i < 1024; i += 256) {
            int r = i >> 3, c = i & 7;
            int sc = (r << 3) + (c ^ (r & 7));
            sh[sc] = gh[i];
            sl[sc] = gl[i];
        }
    }
    __syncthreads();

    unsigned sAhi = (unsigned)__cvta_generic_to_shared(Ahi);
    unsigned sAlo = (unsigned)__cvta_generic_to_shared(Alo);
    unsigned sBhi = (unsigned)__cvta_generic_to_shared(Bhi);
    unsigned sBlo = (unsigned)__cvta_generic_to_shared(Blo);

    // --- hoist A fragments (4 ksteps x 4 regs, hi+lo) — reused by both reps ---
    unsigned ahi[4][4], alo[4][4];
    {
        int m0 = w * 16;
        int r = m0 + (lane & 15);
#pragma unroll
        for (int ks = 0; ks < 4; ks++) {
            int chunk = ks * 2 + (lane >> 4);
            unsigned off = r * 128 + ((chunk ^ (r & 7)) << 4);
            ldsm4(ahi[ks], sAhi + off);
            ldsm4(alo[ks], sAlo + off);
        }
    }

    // per-thread H-producer metadata
    int col = t & 63;
    int kq = t >> 6;  // 0..3 -> k range [kq*16, kq*16+16)
    int brow_base = (lane & 7) + ((lane & 16) >> 1);
    int bksel = (lane >> 3) & 1;

#pragma unroll
    for (int rep = 0; rep < 2; rep++) {
        // --- produce H hi/lo for this column tile ---
        {
            int gcol = (blockIdx.x * 2 + rep) * 64 + col;
            int m = gcol >> 5;
            int knb = gcol & 31;
            int n = g_idx[((size_t)combo * Mn + m) * Kn + knb];
            const float4* Prow = (const float4*)(g_P + ((size_t)(b * 8 + g) * Nn + n) * 64);
            const float4* Arow = (const float4*)(g_A + ((size_t)bs * Mn + m) * 64);
            char* bh = (char*)Bhi;
            char* bl = (char*)Blo;
#pragma unroll
            for (int q = 0; q < 4; q++) {
                float4 p4 = Prow[kq * 4 + q];
                float4 a4 = Arow[kq * 4 + q];
                float h0 = fmaxf(p4.x - a4.x, 0.f);
                float h1 = fmaxf(p4.y - a4.y, 0.f);
                float h2 = fmaxf(p4.z - a4.z, 0.f);
                float h3 = fmaxf(p4.w - a4.w, 0.f);
                __nv_bfloat162 hiA, hiB, loA, loB;
                hiA.x = __float2bfloat16_rn(h0); hiA.y = __float2bfloat16_rn(h1);
                hiB.x = __float2bfloat16_rn(h2); hiB.y = __float2bfloat16_rn(h3);
                loA.x = __float2bfloat16_rn(h0 - __bfloat162float(hiA.x));
                loA.y = __float2bfloat16_rn(h1 - __bfloat162float(hiA.y));
                loB.x = __float2bfloat16_rn(h2 - __bfloat162float(hiB.x));
                loB.y = __float2bfloat16_rn(h3 - __bfloat162float(hiB.y));
                int k0 = kq * 16 + q * 4;
                int chunk = k0 >> 3;
                int off = col * 128 + ((chunk ^ (col & 7)) << 4) + ((k0 & 7) << 1);
                uint2 vh, vl;
                vh.x = *(unsigned*)&hiA; vh.y = *(unsigned*)&hiB;
                vl.x = *(unsigned*)&loA; vl.y = *(unsigned*)&loB;
                *(uint2*)(bh + off) = vh;
                *(uint2*)(bl + off) = vl;
            }
        }
        __syncthreads();

        float acc[8][4];
#pragma unroll
        for (int nt = 0; nt < 8; nt++)
#pragma unroll
            for (int i = 0; i < 4; i++) acc[nt][i] = 0.f;

#pragma unroll
        for (int ks = 0; ks < 4; ks++) {
#pragma unroll
            for (int p = 0; p < 4; p++) {
                int r = p * 16 + brow_base;
                int chunk = ks * 2 + bksel;
                unsigned off = r * 128 + ((chunk ^ (r & 7)) << 4);
                unsigned tmp[4];
                ldsm4(tmp, sBhi + off);
                unsigned bh0 = tmp[0], bh1 = tmp[1];
                unsigned th2 = tmp[2], th3 = tmp[3];
                ldsm4(tmp, sBlo + off);
                mma_bf16(acc[2 * p],     ahi[ks], bh0, bh1);
                mma_bf16(acc[2 * p],     ahi[ks], tmp[0], tmp[1]);
                mma_bf16(acc[2 * p],     alo[ks], bh0, bh1);
                mma_bf16(acc[2 * p + 1], ahi[ks], th2, th3);
                mma_bf16(acc[2 * p + 1], ahi[ks], tmp[2], tmp[3]);
                mma_bf16(acc[2 * p + 1], alo[ks], th2, th3);
            }
        }
        __syncthreads();

        // --- epilogue: per-anchor max over 32 cols via quad shuffles ---
        float* hm = (float*)Bhi;  // scratch [2][128]
#pragma unroll
        for (int a = 0; a < 2; a++) {
            float m0 = -1e30f, m1 = -1e30f;
#pragma unroll
            for (int nt = a * 4; nt < a * 4 + 4; nt++) {
                m0 = fmaxf(m0, fmaxf(acc[nt][0], acc[nt][1]));
                m1 = fmaxf(m1, fmaxf(acc[nt][2], acc[nt][3]));
            }
            m0 = fmaxf(m0, __shfl_xor_sync(0xffffffffu, m0, 1));
            m0 = fmaxf(m0, __shfl_xor_sync(0xffffffffu, m0, 2));
            m1 = fmaxf(m1, __shfl_xor_sync(0xffffffffu, m1, 1));
            m1 = fmaxf(m1, __shfl_xor_sync(0xffffffffu, m1, 2));
            if ((lane & 3) == 0) {
                int grp = lane >> 2;
                hm[a * 128 + w * 16 + grp] = fmaxf(m0, 0.f);
                hm[a * 128 + w * 16 + grp + 8] = fmaxf(m1, 0.f);
            }
        }
        __syncthreads();

        int mbase = (blockIdx.x * 2 + rep) * 2;
        {
            int a = t >> 7, r = t & 127;
            g_hmax[((size_t)combo * Mn + mbase + a) * 128 + r] = hm[a * 128 + r];
        }
        __syncthreads();  // protect hm before next rep overwrites Bhi
    }
}

// ---------------------------------------------------------------------------
// K5: out = sum_j relu(Wt[j] @ hmax[j]) (unchanged)
// ---------------------------------------------------------------------------
__global__ void __launch_bounds__(256) wt_kernel(float* __restrict__ outf) {
    __shared__ float hsh[32 * 128];
    int t = threadIdx.x;
    int bs = blockIdx.y;
    int mbase = blockIdx.x * 32;

    float tot[32];
#pragma unroll
    for (int i = 0; i < 32; i++) tot[i] = 0.f;

    for (int j = 0; j < 3; j++) {
        const float* hb = g_hmax + ((size_t)(bs * 3 + j) * Mn + mbase) * 128;
        for (int i = t; i < 32 * 128; i += 256) hsh[i] = hb[i];
        __syncthreads();

        float acc[32];
#pragma unroll
        for (int i = 0; i < 32; i++) acc[i] = 0.f;

        const float* wtb = g_WtT + (size_t)j * 128 * 256 + t;
        for (int r = 0; r < 128; r += 4) {
            float w0 = wtb[(r + 0) * 256];
            float w1 = wtb[(r + 1) * 256];
            float w2 = wtb[(r + 2) * 256];
            float w3 = wtb[(r + 3) * 256];
#pragma unroll
            for (int mm = 0; mm < 32; mm++) {
                float4 h = *(const float4*)&hsh[mm * 128 + r];
                acc[mm] += w0 * h.x + w1 * h.y + w2 * h.z + w3 * h.w;
            }
        }
#pragma unroll
        for (int i = 0; i < 32; i++) tot[i] += fmaxf(acc[i], 0.f);
        __syncthreads();
    }

    float4* o = (float4*)(outf + ((size_t)bs * 256 + t) * Mn + mbase);
#pragma unroll
    for (int q = 0; q < 8; q++) {
        float4 r;
        r.x = tot[4 * q + 0];
        r.y = tot[4 * q + 1];
        r.z = tot[4 * q + 2];
        r.w = tot[4 * q + 3];
        o[q] = r;
    }
}

// ---------------------------------------------------------------------------
extern "C" void kernel_launch(void* const* d_in, const int* in_sizes, int n_in,
                              void* d_out, int out_size) {
    const float* xyzs = (const float*)d_in[0];
    const float* feats = (const float*)d_in[1];
    const float* Ws0 = (const float*)d_in[2];
    const float* Ws1 = (const float*)d_in[3];
    const float* Wt = (const float*)d_in[4];
    float* out = (float*)d_out;

    const int XYZ_TOTAL = Bn * Sn * Mn * 3;  // 196608

    fps_kernel<<<Bn * Sn, 1024>>>(xyzs, out);                       // 1
    compute_PAW<<<768, 256>>>(xyzs, feats, Ws0, Ws1, Wt);           // 2
    ball_query_kernel<<<dim3(Mn / 8, Bn * Sn * Jn), 256>>>(xyzs);   // 3
    mlp_kernel<<<dim3(Mn * Kn / 128, Bn * Sn * Jn), 256>>>();       // 4 (profiled)
    wt_kernel<<<dim3(Mn / 32, Bn * Sn), 256>>>(out + XYZ_TOTAL);    // 5
}

// round 7
// speedup vs baseline: 1.3636x; 1.0403x over previous
#include <cuda_runtime.h>
#include <cuda_bf16.h>

// Problem constants
#define Bn 4
#define Ln 8
#define Nn 4096
#define Mn 2048
#define Kn 32
#define Sn 8
#define Jn 3

// Staging buffers (device globals; no runtime allocation)
__device__ float g_anchors[Bn * Sn * Mn * 3];
__device__ float g_P[Bn * 8 * Nn * 64];
__device__ float g_A[Bn * Sn * Mn * 64];
__device__ int   g_idx[Bn * Sn * Jn * Mn * Kn];
__device__ float g_hmax[Bn * Sn * Jn * Mn * 128];        // [combo][m][r]
__device__ float g_WtT[Jn * 128 * 256];                  // Wt transposed [j][r][o]
__device__ __nv_bfloat16 g_Ws1hi[128 * 64];              // Ws1 hi, [r][k] row-major
__device__ unsigned g_WsFragLo[8 * 4 * 32 * 4];          // Ws1 lo in mma A-frag layout

// ---------------------------------------------------------------------------
// K1: FPS (known good). One block per (b,s), 1024 threads, coords carried
// through argmax reduction, 2 barriers/iter. No-FMA math.
// ---------------------------------------------------------------------------
__global__ void __launch_bounds__(1024) fps_kernel(const float* __restrict__ xyzs,
                                                   float* __restrict__ out_xyz) {
    int bs = blockIdx.x;
    const float* xyz = xyzs + (size_t)bs * Nn * 3;
    __shared__ float rv[32], rx[32], ry[32], rz[32];
    __shared__ int ri[32];
    __shared__ float scx, scy, scz;

    int t = threadIdx.x;
    int lane = t & 31, wid = t >> 5;

    float px[4], py[4], pz[4], pd[4];
#pragma unroll
    for (int i = 0; i < 4; i++) {
        int p = t + i * 1024;
        px[i] = xyz[3 * p]; py[i] = xyz[3 * p + 1]; pz[i] = xyz[3 * p + 2];
        pd[i] = 1e10f;
    }
    if (t == 0) { scx = px[0]; scy = py[0]; scz = pz[0]; }
    __syncthreads();

    float* oanc = g_anchors + (size_t)bs * Mn * 3;
    float* oxyz = out_xyz + (size_t)bs * Mn * 3;

    for (int m = 0; m < Mn; m++) {
        float cx = scx, cy = scy, cz = scz;
        if (t == 0) {
            oanc[3 * m] = cx; oanc[3 * m + 1] = cy; oanc[3 * m + 2] = cz;
            oxyz[3 * m] = cx; oxyz[3 * m + 1] = cy; oxyz[3 * m + 2] = cz;
        }
        float best = -1.0f, bx = 0.f, by = 0.f, bz = 0.f;
        int bi = 0;
#pragma unroll
        for (int i = 0; i < 4; i++) {
            float dx = __fsub_rn(px[i], cx);
            float dy = __fsub_rn(py[i], cy);
            float dz = __fsub_rn(pz[i], cz);
            float d = __fadd_rn(__fadd_rn(__fmul_rn(dx, dx), __fmul_rn(dy, dy)),
                                __fmul_rn(dz, dz));
            float nd = fminf(pd[i], d);
            pd[i] = nd;
            if (nd > best) { best = nd; bi = t + i * 1024; bx = px[i]; by = py[i]; bz = pz[i]; }
        }
#pragma unroll
        for (int off = 16; off > 0; off >>= 1) {
            float v = __shfl_xor_sync(0xffffffffu, best, off);
            int j2 = __shfl_xor_sync(0xffffffffu, bi, off);
            float x2 = __shfl_xor_sync(0xffffffffu, bx, off);
            float y2 = __shfl_xor_sync(0xffffffffu, by, off);
            float z2 = __shfl_xor_sync(0xffffffffu, bz, off);
            if (v > best || (v == best && j2 < bi)) { best = v; bi = j2; bx = x2; by = y2; bz = z2; }
        }
        if (lane == 0) { rv[wid] = best; ri[wid] = bi; rx[wid] = bx; ry[wid] = by; rz[wid] = bz; }
        __syncthreads();
        if (wid == 0) {
            best = rv[lane]; bi = ri[lane]; bx = rx[lane]; by = ry[lane]; bz = rz[lane];
#pragma unroll
            for (int off = 16; off > 0; off >>= 1) {
                float v = __shfl_xor_sync(0xffffffffu, best, off);
                int j2 = __shfl_xor_sync(0xffffffffu, bi, off);
                float x2 = __shfl_xor_sync(0xffffffffu, bx, off);
                float y2 = __shfl_xor_sync(0xffffffffu, by, off);
                float z2 = __shfl_xor_sync(0xffffffffu, bz, off);
                if (v > best || (v == best && j2 < bi)) { best = v; bi = j2; bx = x2; by = y2; bz = z2; }
            }
            if (lane == 0) { scx = bx; scy = by; scz = bz; }
        }
        __syncthreads();
    }
}

// ---------------------------------------------------------------------------
// K2: merged P + A + weight prep.
// ---------------------------------------------------------------------------
__global__ void __launch_bounds__(256) compute_PAW(const float* __restrict__ xyzs,
                                                   const float* __restrict__ feats,
                                                   const float* __restrict__ Ws0,
                                                   const float* __restrict__ Ws1,
                                                   const float* __restrict__ Wt) {
    int t = threadIdx.x;
    if (blockIdx.x < 512) {
        __shared__ float w[64 * 6];
        for (int i = t; i < 64 * 6; i += 256) w[i] = Ws0[i];
        __syncthreads();

        int gp = blockIdx.x * 256 + t;
        int n = gp & (Nn - 1);
        int bf = gp >> 12;
        const float* p = xyzs + (size_t)gp * 3;
        float x = p[0], y = p[1], z = p[2];
        const float* f = feats + (size_t)bf * 3 * Nn + n;
        float f0 = f[0], f1 = f[Nn], f2 = f[2 * Nn];
        float4* o = (float4*)(g_P + (size_t)gp * 64);
#pragma unroll
        for (int oo = 0; oo < 64; oo += 4) {
            float4 r;
            const float* w0 = w + oo * 6;
            r.x = w0[0] * x + w0[1] * y + w0[2] * z + w0[3] * f0 + w0[4] * f1 + w0[5] * f2;
            r.y = w0[6] * x + w0[7] * y + w0[8] * z + w0[9] * f0 + w0[10] * f1 + w0[11] * f2;
            r.z = w0[12] * x + w0[13] * y + w0[14] * z + w0[15] * f0 + w0[16] * f1 + w0[17] * f2;
            r.w = w0[18] * x + w0[19] * y + w0[20] * z + w0[21] * f0 + w0[22] * f1 + w0[23] * f2;
            o[oo >> 2] = r;
        }
    } else {
        __shared__ float w[64 * 3];
        for (int i = t; i < 64 * 3; i += 256) {
            int o = i / 3, c = i % 3;
            w[i] = Ws0[o * 6 + c];
        }
        __syncthreads();
        int ga = (blockIdx.x - 512) * 256 + t;  // 0..65535
        const float* a = g_anchors + (size_t)ga * 3;
        float x = a[0], y = a[1], z = a[2];
        float4* o = (float4*)(g_A + (size_t)ga * 64);
#pragma unroll
        for (int oo = 0; oo < 64; oo += 4) {
            float4 r;
            const float* w0 = w + oo * 3;
            r.x = w0[0] * x + w0[1] * y + w0[2] * z;
            r.y = w0[3] * x + w0[4] * y + w0[5] * z;
            r.z = w0[6] * x + w0[7] * y + w0[8] * z;
            r.w = w0[9] * x + w0[10] * y + w0[11] * z;
            o[oo >> 2] = r;
        }
        // weight prep, spread across these 65536 threads
        for (int i = ga; i < Jn * 256 * 128; i += 65536) {
            int j = i / (256 * 128);
            int rem = i % (256 * 128);
            int oo = rem / 128, r = rem % 128;
            g_WtT[(j * 128 + r) * 256 + oo] = Wt[i];
        }
        if (ga < 128 * 64) {
            float ww = Ws1[ga];
            g_Ws1hi[ga] = __float2bfloat16_rn(ww);
        }
        if (ga < 8 * 4 * 32 * 4) {
            // A-frag lo packing: (w, ks, lane, q)
            int q = ga & 3, lane = (ga >> 2) & 31, ks = (ga >> 7) & 3, w8 = ga >> 9;
            int row = w8 * 16 + (lane >> 2) + (q & 1) * 8;
            int k = ks * 16 + (lane & 3) * 2 + ((q >> 1) & 1) * 8;
            float e0 = Ws1[row * 64 + k];
            float e1 = Ws1[row * 64 + k + 1];
            __nv_bfloat16 h0 = __float2bfloat16_rn(e0);
            __nv_bfloat16 h1 = __float2bfloat16_rn(e1);
            __nv_bfloat16 l0 = __float2bfloat16_rn(e0 - __bfloat162float(h0));
            __nv_bfloat16 l1 = __float2bfloat16_rn(e1 - __bfloat162float(h1));
            unsigned ul0 = *(unsigned short*)&l0, ul1 = *(unsigned short*)&l1;
            g_WsFragLo[ga] = (ul1 << 16) | ul0;
        }
    }
}

// ---------------------------------------------------------------------------
// K3: ball query (unchanged)
// ---------------------------------------------------------------------------
__global__ void __launch_bounds__(256) ball_query_kernel(const float* __restrict__ xyzs) {
    int combo = blockIdx.y;
    int j = combo % 3;
    int bs = combo / 3;
    int b = bs >> 3, s = bs & 7;
    int g = s - 1 + j;
    g = g < 0 ? 0 : (g > 7 ? 7 : g);
    int wid = threadIdx.x >> 5, lane = threadIdx.x & 31;
    int m = blockIdx.x * 8 + wid;

    const float* pts = xyzs + (size_t)(b * 8 + g) * Nn * 3;
    const float* anc = g_anchors + ((size_t)bs * Mn + m) * 3;
    float ax = anc[0], ay = anc[1], az = anc[2];
    int* out = g_idx + ((size_t)combo * Mn + m) * Kn;

    int found = 0, first = -1;
    unsigned lt = (1u << lane) - 1u;
    for (int base = 0; base < Nn && found < Kn; base += 32) {
        int n = base + lane;
        const float* pp = pts + 3 * n;
        float dx = __fsub_rn(pp[0], ax);
        float dy = __fsub_rn(pp[1], ay);
        float dz = __fsub_rn(pp[2], az);
        float d2 = __fadd_rn(__fadd_rn(__fmul_rn(dx, dx), __fmul_rn(dy, dy)),
                             __fmul_rn(dz, dz));
        bool pred = d2 < 0.25f;
        unsigned msk = __ballot_sync(0xffffffffu, pred);
        if (first < 0 && msk) first = base + (__ffs(msk) - 1);
        int pos = found + __popc(msk & lt);
        if (pred && pos < Kn) out[pos] = n;
        found += __popc(msk);
    }
    if (found < Kn) {
        int pad = first < 0 ? 0 : first;
        for (int p = found + lane; p < Kn; p += 32) out[p] = pad;
    }
}

// ---------------------------------------------------------------------------
// K4: layer-1 GEMM on tensor cores, software-pipelined double buffer.
// Per block: 4 reps x (128 rows x 64 cols), K=64.
// smem: Whi 16KB + 2x(Bhi 8KB + Blo 8KB) = 48KB exactly.
// Schedule per rep: prefetch next H rows (LDG) -> mma current buffer ->
// convert+STS next buffer -> epilogue (shuffle max, direct gmem store) ->
// one __syncthreads.
// ---------------------------------------------------------------------------
__device__ __forceinline__ void mma_bf16(float c[4], const unsigned a[4],
                                         unsigned b0, unsigned b1) {
    asm volatile(
        "mma.sync.aligned.m16n8k16.row.col.f32.bf16.bf16.f32 "
        "{%0,%1,%2,%3}, {%4,%5,%6,%7}, {%8,%9}, {%0,%1,%2,%3};"
        : "+f"(c[0]), "+f"(c[1]), "+f"(c[2]), "+f"(c[3])
        : "r"(a[0]), "r"(a[1]), "r"(a[2]), "r"(a[3]), "r"(b0), "r"(b1));
}

__device__ __forceinline__ void ldsm4(unsigned r[4], unsigned saddr) {
    asm volatile(
        "ldmatrix.sync.aligned.m8n8.x4.shared.b16 {%0,%1,%2,%3}, [%4];"
        : "=r"(r[0]), "=r"(r[1]), "=r"(r[2]), "=r"(r[3])
        : "r"(saddr));
}

#define MLP_REPS 4

__global__ void __launch_bounds__(256) mlp_kernel() {
    __shared__ __align__(16) __nv_bfloat16 Whi[128 * 64];    // 16KB [r][k] swizzled
    __shared__ __align__(16) __nv_bfloat16 Bhs[2][64 * 64];  // 2x8KB [col][k] swizzled
    __shared__ __align__(16) __nv_bfloat16 Bls[2][64 * 64];  // 2x8KB

    int t = threadIdx.x;
    int lane = t & 31, w = t >> 5;
    int combo = blockIdx.y;
    int j = combo % 3;
    int bs = combo / 3;
    int b = bs >> 3, s = bs & 7;
    int g = s - 1 + j;
    g = g < 0 ? 0 : (g > 7 ? 7 : g);

    // --- load W hi into smem (swizzled) ---
    {
        const uint4* gh = (const uint4*)g_Ws1hi;  // 1024 x 16B
        uint4* sh = (uint4*)Whi;
        for (int i = t; i < 1024; i += 256) {
            int r = i >> 3, c = i & 7;
            sh[(r << 3) + (c ^ (r & 7))] = gh[i];
        }
    }
    __syncthreads();

    unsigned sWhi = (unsigned)__cvta_generic_to_shared(Whi);
    unsigned sBh0 = (unsigned)__cvta_generic_to_shared(Bhs[0]);
    unsigned sBl0 = (unsigned)__cvta_generic_to_shared(Bls[0]);

    // --- hoist A fragments: hi via ldsm from smem, lo via coalesced LDG ---
    unsigned ahi[4][4], alo[4][4];
    {
        int r = w * 16 + (lane & 15);
#pragma unroll
        for (int ks = 0; ks < 4; ks++) {
            int chunk = ks * 2 + (lane >> 4);
            ldsm4(ahi[ks], sWhi + r * 128 + ((chunk ^ (r & 7)) << 4));
            uint4 fl = ((const uint4*)g_WsFragLo)[(w * 4 + ks) * 32 + lane];
            alo[ks][0] = fl.x; alo[ks][1] = fl.y; alo[ks][2] = fl.z; alo[ks][3] = fl.w;
        }
    }

    // per-thread H-producer metadata
    int col = t & 63;
    int kq = t >> 6;  // k range [kq*16, kq*16+16)
    int brow_base = (lane & 7) + ((lane & 16) >> 1);
    int bksel = (lane >> 3) & 1;

    const float4* Pbase = (const float4*)(g_P + (size_t)(b * 8 + g) * Nn * 64);
    const float4* Abase = (const float4*)(g_A + (size_t)bs * Mn * 64);
    const int* idxbase = g_idx + (size_t)combo * Mn * Kn;

    float4 pf_p[4], pf_a[4];

    // prefetch + fill buffer 0
    {
        int gcol = blockIdx.x * MLP_REPS * 64 + col;
        int m = gcol >> 5, knb = gcol & 31;
        int n = idxbase[m * Kn + knb];
        const float4* Prow = Pbase + (size_t)n * 16;
        const float4* Arow = Abase + (size_t)m * 16;
#pragma unroll
        for (int q = 0; q < 4; q++) { pf_p[q] = Prow[kq * 4 + q]; pf_a[q] = Arow[kq * 4 + q]; }
    }
    {
        char* bh = (char*)Bhs[0];
        char* bl = (char*)Bls[0];
#pragma unroll
        for (int q = 0; q < 4; q++) {
            float h0 = fmaxf(pf_p[q].x - pf_a[q].x, 0.f);
            float h1 = fmaxf(pf_p[q].y - pf_a[q].y, 0.f);
            float h2 = fmaxf(pf_p[q].z - pf_a[q].z, 0.f);
            float h3 = fmaxf(pf_p[q].w - pf_a[q].w, 0.f);
            __nv_bfloat162 hiA, hiB, loA, loB;
            hiA.x = __float2bfloat16_rn(h0); hiA.y = __float2bfloat16_rn(h1);
            hiB.x = __float2bfloat16_rn(h2); hiB.y = __float2bfloat16_rn(h3);
            loA.x = __float2bfloat16_rn(h0 - __bfloat162float(hiA.x));
            loA.y = __float2bfloat16_rn(h1 - __bfloat162float(hiA.y));
            loB.x = __float2bfloat16_rn(h2 - __bfloat162float(hiB.x));
            loB.y = __float2bfloat16_rn(h3 - __bfloat162float(hiB.y));
            int k0 = kq * 16 + q * 4;
            int chunk = k0 >> 3;
            int off = col * 128 + ((chunk ^ (col & 7)) << 4) + ((k0 & 7) << 1);
            uint2 vh, vl;
            vh.x = *(unsigned*)&hiA; vh.y = *(unsigned*)&hiB;
            vl.x = *(unsigned*)&loA; vl.y = *(unsigned*)&loB;
            *(uint2*)(bh + off) = vh;
            *(uint2*)(bl + off) = vl;
        }
    }
    __syncthreads();

#pragma unroll
    for (int rep = 0; rep < MLP_REPS; rep++) {
        int buf = rep & 1;
        // --- prefetch next rep's rows (long-latency LDGs first) ---
        if (rep + 1 < MLP_REPS) {
            int gcol = (blockIdx.x * MLP_REPS + rep + 1) * 64 + col;
            int m = gcol >> 5, knb = gcol & 31;
            int n = idxbase[m * Kn + knb];
            const float4* Prow = Pbase + (size_t)n * 16;
            const float4* Arow = Abase + (size_t)m * 16;
#pragma unroll
            for (int q = 0; q < 4; q++) { pf_p[q] = Prow[kq * 4 + q]; pf_a[q] = Arow[kq * 4 + q]; }
        }

        // --- mma on current buffer ---
        float acc[8][4];
#pragma unroll
        for (int nt = 0; nt < 8; nt++)
#pragma unroll
            for (int i = 0; i < 4; i++) acc[nt][i] = 0.f;

        unsigned sBh = sBh0 + buf * 8192;
        unsigned sBl = sBl0 + buf * 8192;
#pragma unroll
        for (int ks = 0; ks < 4; ks++) {
#pragma unroll
            for (int p = 0; p < 4; p++) {
                int r = p * 16 + brow_base;
                int chunk = ks * 2 + bksel;
                unsigned off = r * 128 + ((chunk ^ (r & 7)) << 4);
                unsigned tmp[4];
                ldsm4(tmp, sBh + off);
                unsigned bh0 = tmp[0], bh1 = tmp[1];
                unsigned th2 = tmp[2], th3 = tmp[3];
                ldsm4(tmp, sBl + off);
                mma_bf16(acc[2 * p],     ahi[ks], bh0, bh1);
                mma_bf16(acc[2 * p],     ahi[ks], tmp[0], tmp[1]);
                mma_bf16(acc[2 * p],     alo[ks], bh0, bh1);
                mma_bf16(acc[2 * p + 1], ahi[ks], th2, th3);
                mma_bf16(acc[2 * p + 1], ahi[ks], tmp[2], tmp[3]);
                mma_bf16(acc[2 * p + 1], alo[ks], th2, th3);
            }
        }

        // --- convert + STS prefetched rows into the other buffer ---
        if (rep + 1 < MLP_REPS) {
            char* bh = (char*)Bhs[buf ^ 1];
            char* bl = (char*)Bls[buf ^ 1];
#pragma unroll
            for (int q = 0; q < 4; q++) {
                float h0 = fmaxf(pf_p[q].x - pf_a[q].x, 0.f);
                float h1 = fmaxf(pf_p[q].y - pf_a[q].y, 0.f);
                float h2 = fmaxf(pf_p[q].z - pf_a[q].z, 0.f);
                float h3 = fmaxf(pf_p[q].w - pf_a[q].w, 0.f);
                __nv_bfloat162 hiA, hiB, loA, loB;
                hiA.x = __float2bfloat16_rn(h0); hiA.y = __float2bfloat16_rn(h1);
                hiB.x = __float2bfloat16_rn(h2); hiB.y = __float2bfloat16_rn(h3);
                loA.x = __float2bfloat16_rn(h0 - __bfloat162float(hiA.x));
                loA.y = __float2bfloat16_rn(h1 - __bfloat162float(hiA.y));
                loB.x = __float2bfloat16_rn(h2 - __bfloat162float(hiB.x));
                loB.y = __float2bfloat16_rn(h3 - __bfloat162float(hiB.y));
                int k0 = kq * 16 + q * 4;
                int chunk = k0 >> 3;
                int off = col * 128 + ((chunk ^ (col & 7)) << 4) + ((k0 & 7) << 1);
                uint2 vh, vl;
                vh.x = *(unsigned*)&hiA; vh.y = *(unsigned*)&hiB;
                vl.x = *(unsigned*)&loA; vl.y = *(unsigned*)&loB;
                *(uint2*)(bh + off) = vh;
                *(uint2*)(bl + off) = vl;
            }
        }

        // --- epilogue: per-anchor max over 32 cols via quad shuffles,
        //     direct gmem stores (no scratch, no extra barrier) ---
        int mbase = (blockIdx.x * MLP_REPS + rep) * 2;
        int grp = lane >> 2;
#pragma unroll
        for (int a = 0; a < 2; a++) {
            float m0 = -1e30f, m1 = -1e30f;
#pragma unroll
            for (int nt = a * 4; nt < a * 4 + 4; nt++) {
                m0 = fmaxf(m0, fmaxf(acc[nt][0], acc[nt][1]));
                m1 = fmaxf(m1, fmaxf(acc[nt][2], acc[nt][3]));
            }
            m0 = fmaxf(m0, __shfl_xor_sync(0xffffffffu, m0, 1));
            m0 = fmaxf(m0, __shfl_xor_sync(0xffffffffu, m0, 2));
            m1 = fmaxf(m1, __shfl_xor_sync(0xffffffffu, m1, 1));
            m1 = fmaxf(m1, __shfl_xor_sync(0xffffffffu, m1, 2));
            if ((lane & 3) == 0) {
                float* o = g_hmax + ((size_t)combo * Mn + mbase + a) * 128 + w * 16 + grp;
                o[0] = fmaxf(m0, 0.f);
                o[8] = fmaxf(m1, 0.f);
            }
        }
        __syncthreads();
    }
}

// ---------------------------------------------------------------------------
// K5: out = sum_j relu(Wt[j] @ hmax[j]) (unchanged)
// ---------------------------------------------------------------------------
__global__ void __launch_bounds__(256) wt_kernel(float* __restrict__ outf) {
    __shared__ float hsh[32 * 128];
    int t = threadIdx.x;
    int bs = blockIdx.y;
    int mbase = blockIdx.x * 32;

    float tot[32];
#pragma unroll
    for (int i = 0; i < 32; i++) tot[i] = 0.f;

    for (int j = 0; j < 3; j++) {
        const float* hb = g_hmax + ((size_t)(bs * 3 + j) * Mn + mbase) * 128;
        for (int i = t; i < 32 * 128; i += 256) hsh[i] = hb[i];
        __syncthreads();

        float acc[32];
#pragma unroll
        for (int i = 0; i < 32; i++) acc[i] = 0.f;

        const float* wtb = g_WtT + (size_t)j * 128 * 256 + t;
        for (int r = 0; r < 128; r += 4) {
            float w0 = wtb[(r + 0) * 256];
            float w1 = wtb[(r + 1) * 256];
            float w2 = wtb[(r + 2) * 256];
            float w3 = wtb[(r + 3) * 256];
#pragma unroll
            for (int mm = 0; mm < 32; mm++) {
                float4 h = *(const float4*)&hsh[mm * 128 + r];
                acc[mm] += w0 * h.x + w1 * h.y + w2 * h.z + w3 * h.w;
            }
        }
#pragma unroll
        for (int i = 0; i < 32; i++) tot[i] += fmaxf(acc[i], 0.f);
        __syncthreads();
    }

    float4* o = (float4*)(outf + ((size_t)bs * 256 + t) * Mn + mbase);
#pragma unroll
    for (int q = 0; q < 8; q++) {
        float4 r;
        r.x = tot[4 * q + 0];
        r.y = tot[4 * q + 1];
        r.z = tot[4 * q + 2];
        r.w = tot[4 * q + 3];
        o[q] = r;
    }
}

// ---------------------------------------------------------------------------
extern "C" void kernel_launch(void* const* d_in, const int* in_sizes, int n_in,
                              void* d_out, int out_size) {
    const float* xyzs = (const float*)d_in[0];
    const float* feats = (const float*)d_in[1];
    const float* Ws0 = (const float*)d_in[2];
    const float* Ws1 = (const float*)d_in[3];
    const float* Wt = (const float*)d_in[4];
    float* out = (float*)d_out;

    const int XYZ_TOTAL = Bn * Sn * Mn * 3;  // 196608

    fps_kernel<<<Bn * Sn, 1024>>>(xyzs, out);                               // 1
    compute_PAW<<<768, 256>>>(xyzs, feats, Ws0, Ws1, Wt);                   // 2
    ball_query_kernel<<<dim3(Mn / 8, Bn * Sn * Jn), 256>>>(xyzs);           // 3
    mlp_kernel<<<dim3(Mn * Kn / (64 * MLP_REPS), Bn * Sn * Jn), 256>>>();   // 4 (profiled)
    wt_kernel<<<dim3(Mn / 32, Bn * Sn), 256>>>(out + XYZ_TOTAL);            // 5
}

// round 8
// speedup vs baseline: 1.8459x; 1.3537x over previous
#include <cuda_runtime.h>
#include <cuda_bf16.h>

// Problem constants
#define Bn 4
#define Ln 8
#define Nn 4096
#define Mn 2048
#define Kn 32
#define Sn 8
#define Jn 3

// Staging buffers (device globals; no runtime allocation)
__device__ float g_anchors[Bn * Sn * Mn * 3];
__device__ float g_P[Bn * 8 * Nn * 64];
__device__ float g_A[Bn * Sn * Mn * 64];
__device__ int   g_idx[Bn * Sn * Jn * Mn * Kn];
__device__ float g_hmax[Bn * Sn * Jn * Mn * 128];        // [combo][m][r]
__device__ __nv_bfloat16 g_Ws1hi[128 * 64];              // Ws1 hi, [r][k] row-major
__device__ unsigned g_WsFragLo[8 * 4 * 32 * 4];          // Ws1 lo in mma A-frag layout
__device__ unsigned g_WtFragHi[3 * 16 * 8 * 32 * 4];     // Wt hi in mma A-frag layout
__device__ unsigned g_WtFragLo[3 * 16 * 8 * 32 * 4];     // Wt lo

// ---------------------------------------------------------------------------
// P1: Ws1 prep (hi table + lo A-frags) — also serves as pre-fps launch #1
// ---------------------------------------------------------------------------
__global__ void __launch_bounds__(256) wsprep(const float* __restrict__ Ws1) {
    int t = blockIdx.x * 256 + threadIdx.x;
    if (t < 128 * 64) {
        g_Ws1hi[t] = __float2bfloat16_rn(Ws1[t]);
    }
    if (t < 8 * 4 * 32 * 4) {
        int q = t & 3, lane = (t >> 2) & 31, ks = (t >> 7) & 3, w8 = t >> 9;
        int row = w8 * 16 + (lane >> 2) + (q & 1) * 8;
        int k = ks * 16 + (lane & 3) * 2 + ((q >> 1) & 1) * 8;
        float e0 = Ws1[row * 64 + k];
        float e1 = Ws1[row * 64 + k + 1];
        __nv_bfloat16 h0 = __float2bfloat16_rn(e0);
        __nv_bfloat16 h1 = __float2bfloat16_rn(e1);
        __nv_bfloat16 l0 = __float2bfloat16_rn(e0 - __bfloat162float(h0));
        __nv_bfloat16 l1 = __float2bfloat16_rn(e1 - __bfloat162float(h1));
        unsigned ul0 = *(unsigned short*)&l0, ul1 = *(unsigned short*)&l1;
        g_WsFragLo[t] = (ul1 << 16) | ul0;
    }
}

// ---------------------------------------------------------------------------
// P2/P3: Wt A-frag packing (hi / lo). i -> (j, rb, ks, lane, q).
// row = rb*16 + (lane>>2) + (q&1)*8; k = ks*16 + (lane&3)*2 + ((q>>1)&1)*8.
// ---------------------------------------------------------------------------
__global__ void __launch_bounds__(256) wtfrag_hi(const float* __restrict__ Wt) {
    int i = blockIdx.x * 256 + threadIdx.x;  // < 49152
    int q = i & 3, lane = (i >> 2) & 31, ks = (i >> 7) & 7, rb = (i >> 10) & 15, j = i >> 14;
    int row = rb * 16 + (lane >> 2) + (q & 1) * 8;
    int k = ks * 16 + (lane & 3) * 2 + ((q >> 1) & 1) * 8;
    float e0 = Wt[(j * 256 + row) * 128 + k];
    float e1 = Wt[(j * 256 + row) * 128 + k + 1];
    __nv_bfloat16 h0 = __float2bfloat16_rn(e0);
    __nv_bfloat16 h1 = __float2bfloat16_rn(e1);
    unsigned u0 = *(unsigned short*)&h0, u1 = *(unsigned short*)&h1;
    g_WtFragHi[i] = (u1 << 16) | u0;
}

__global__ void __launch_bounds__(256) wtfrag_lo(const float* __restrict__ Wt) {
    int i = blockIdx.x * 256 + threadIdx.x;
    int q = i & 3, lane = (i >> 2) & 31, ks = (i >> 7) & 7, rb = (i >> 10) & 15, j = i >> 14;
    int row = rb * 16 + (lane >> 2) + (q & 1) * 8;
    int k = ks * 16 + (lane & 3) * 2 + ((q >> 1) & 1) * 8;
    float e0 = Wt[(j * 256 + row) * 128 + k];
    float e1 = Wt[(j * 256 + row) * 128 + k + 1];
    __nv_bfloat16 h0 = __float2bfloat16_rn(e0);
    __nv_bfloat16 h1 = __float2bfloat16_rn(e1);
    __nv_bfloat16 l0 = __float2bfloat16_rn(e0 - __bfloat162float(h0));
    __nv_bfloat16 l1 = __float2bfloat16_rn(e1 - __bfloat162float(h1));
    unsigned u0 = *(unsigned short*)&l0, u1 = *(unsigned short*)&l1;
    g_WtFragLo[i] = (u1 << 16) | u0;
}

// ---------------------------------------------------------------------------
// K1: FPS, 256 threads x 16 points, packed u64 argmax keys
// (distbits<<32 | ~idx — exact argmax + smallest-index tie-break, verified
// in R5), ONE barrier per iter (double-buffered 8-slot key array, all
// threads reduce redundantly). Winner coords via broadcast L1 LDG.
// No-FMA arithmetic: ((dx*dx + dy*dy) + dz*dz).
// ---------------------------------------------------------------------------
__global__ void __launch_bounds__(256) fps_kernel(const float* __restrict__ xyzs,
                                                  float* __restrict__ out_xyz) {
    int bs = blockIdx.x;
    const float* xyz = xyzs + (size_t)bs * Nn * 3;
    __shared__ unsigned long long skey[2][8];

    int t = threadIdx.x;
    int lane = t & 31, wid = t >> 5;

    float px[16], py[16], pz[16], pd[16];
#pragma unroll
    for (int i = 0; i < 16; i++) {
        int p = t + i * 256;
        px[i] = xyz[3 * p]; py[i] = xyz[3 * p + 1]; pz[i] = xyz[3 * p + 2];
        pd[i] = 1e10f;
    }
    float cx = xyz[0], cy = xyz[1], cz = xyz[2];

    float* oanc = g_anchors + (size_t)bs * Mn * 3;
    float* oxyz = out_xyz + (size_t)bs * Mn * 3;

    for (int m = 0; m < Mn; m++) {
        if (t == 0) {
            oanc[3 * m] = cx; oanc[3 * m + 1] = cy; oanc[3 * m + 2] = cz;
            oxyz[3 * m] = cx; oxyz[3 * m + 1] = cy; oxyz[3 * m + 2] = cz;
        }
        unsigned long long key = 0;
#pragma unroll
        for (int i = 0; i < 16; i++) {
            float dx = __fsub_rn(px[i], cx);
            float dy = __fsub_rn(py[i], cy);
            float dz = __fsub_rn(pz[i], cz);
            float d = __fadd_rn(__fadd_rn(__fmul_rn(dx, dx), __fmul_rn(dy, dy)),
                                __fmul_rn(dz, dz));
            float nd = fminf(pd[i], d);
            pd[i] = nd;
            unsigned long long k =
                ((unsigned long long)__float_as_uint(nd) << 32) |
                (unsigned)(0xFFFFFFFFu - (unsigned)(t + i * 256));
            key = (k > key) ? k : key;
        }
#pragma unroll
        for (int off = 16; off > 0; off >>= 1) {
            unsigned long long k2 = __shfl_xor_sync(0xffffffffu, key, off);
            key = (k2 > key) ? k2 : key;
        }
        if (lane == 0) skey[m & 1][wid] = key;
        __syncthreads();
        unsigned long long kb = skey[m & 1][0];
#pragma unroll
        for (int wq = 1; wq < 8; wq++) {
            unsigned long long k2 = skey[m & 1][wq];
            kb = (k2 > kb) ? k2 : kb;
        }
        int widx = (int)(0xFFFFFFFFu - (unsigned)kb);
        cx = xyz[3 * widx]; cy = xyz[3 * widx + 1]; cz = xyz[3 * widx + 2];
    }
}

// ---------------------------------------------------------------------------
// K2: P (blocks [0,512)) + A (blocks [512,768)) projections.
// ---------------------------------------------------------------------------
__global__ void __launch_bounds__(256) compute_PA(const float* __restrict__ xyzs,
                                                  const float* __restrict__ feats,
                                                  const float* __restrict__ Ws0) {
    int t = threadIdx.x;
    if (blockIdx.x < 512) {
        __shared__ float w[64 * 6];
        for (int i = t; i < 64 * 6; i += 256) w[i] = Ws0[i];
        __syncthreads();

        int gp = blockIdx.x * 256 + t;
        int n = gp & (Nn - 1);
        int bf = gp >> 12;
        const float* p = xyzs + (size_t)gp * 3;
        float x = p[0], y = p[1], z = p[2];
        const float* f = feats + (size_t)bf * 3 * Nn + n;
        float f0 = f[0], f1 = f[Nn], f2 = f[2 * Nn];
        float4* o = (float4*)(g_P + (size_t)gp * 64);
#pragma unroll
        for (int oo = 0; oo < 64; oo += 4) {
            float4 r;
            const float* w0 = w + oo * 6;
            r.x = w0[0] * x + w0[1] * y + w0[2] * z + w0[3] * f0 + w0[4] * f1 + w0[5] * f2;
            r.y = w0[6] * x + w0[7] * y + w0[8] * z + w0[9] * f0 + w0[10] * f1 + w0[11] * f2;
            r.z = w0[12] * x + w0[13] * y + w0[14] * z + w0[15] * f0 + w0[16] * f1 + w0[17] * f2;
            r.w = w0[18] * x + w0[19] * y + w0[20] * z + w0[21] * f0 + w0[22] * f1 + w0[23] * f2;
            o[oo >> 2] = r;
        }
    } else {
        __shared__ float w[64 * 3];
        for (int i = t; i < 64 * 3; i += 256) {
            int o = i / 3, c = i % 3;
            w[i] = Ws0[o * 6 + c];
        }
        __syncthreads();
        int ga = (blockIdx.x - 512) * 256 + t;
        const float* a = g_anchors + (size_t)ga * 3;
        float x = a[0], y = a[1], z = a[2];
        float4* o = (float4*)(g_A + (size_t)ga * 64);
#pragma unroll
        for (int oo = 0; oo < 64; oo += 4) {
            float4 r;
            const float* w0 = w + oo * 3;
            r.x = w0[0] * x + w0[1] * y + w0[2] * z;
            r.y = w0[3] * x + w0[4] * y + w0[5] * z;
            r.z = w0[6] * x + w0[7] * y + w0[8] * z;
            r.w = w0[9] * x + w0[10] * y + w0[11] * z;
            o[oo >> 2] = r;
        }
    }
}

// ---------------------------------------------------------------------------
// K3: ball query (unchanged)
// ---------------------------------------------------------------------------
__global__ void __launch_bounds__(256) ball_query_kernel(const float* __restrict__ xyzs) {
    int combo = blockIdx.y;
    int j = combo % 3;
    int bs = combo / 3;
    int b = bs >> 3, s = bs & 7;
    int g = s - 1 + j;
    g = g < 0 ? 0 : (g > 7 ? 7 : g);
    int wid = threadIdx.x >> 5, lane = threadIdx.x & 31;
    int m = blockIdx.x * 8 + wid;

    const float* pts = xyzs + (size_t)(b * 8 + g) * Nn * 3;
    const float* anc = g_anchors + ((size_t)bs * Mn + m) * 3;
    float ax = anc[0], ay = anc[1], az = anc[2];
    int* out = g_idx + ((size_t)combo * Mn + m) * Kn;

    int found = 0, first = -1;
    unsigned lt = (1u << lane) - 1u;
    for (int base = 0; base < Nn && found < Kn; base += 32) {
        int n = base + lane;
        const float* pp = pts + 3 * n;
        float dx = __fsub_rn(pp[0], ax);
        float dy = __fsub_rn(pp[1], ay);
        float dz = __fsub_rn(pp[2], az);
        float d2 = __fadd_rn(__fadd_rn(__fmul_rn(dx, dx), __fmul_rn(dy, dy)),
                             __fmul_rn(dz, dz));
        bool pred = d2 < 0.25f;
        unsigned msk = __ballot_sync(0xffffffffu, pred);
        if (first < 0 && msk) first = base + (__ffs(msk) - 1);
        int pos = found + __popc(msk & lt);
        if (pred && pos < Kn) out[pos] = n;
        found += __popc(msk);
    }
    if (found < Kn) {
        int pad = first < 0 ? 0 : first;
        for (int p = found + lane; p < Kn; p += 32) out[p] = pad;
    }
}

// ---------------------------------------------------------------------------
// mma / ldsm helpers
// ---------------------------------------------------------------------------
__device__ __forceinline__ void mma_bf16(float c[4], const unsigned a[4],
                                         unsigned b0, unsigned b1) {
    asm volatile(
        "mma.sync.aligned.m16n8k16.row.col.f32.bf16.bf16.f32 "
        "{%0,%1,%2,%3}, {%4,%5,%6,%7}, {%8,%9}, {%0,%1,%2,%3};"
        : "+f"(c[0]), "+f"(c[1]), "+f"(c[2]), "+f"(c[3])
        : "r"(a[0]), "r"(a[1]), "r"(a[2]), "r"(a[3]), "r"(b0), "r"(b1));
}

__device__ __forceinline__ void ldsm4(unsigned r[4], unsigned saddr) {
    asm volatile(
        "ldmatrix.sync.aligned.m8n8.x4.shared.b16 {%0,%1,%2,%3}, [%4];"
        : "=r"(r[0]), "=r"(r[1]), "=r"(r[2]), "=r"(r[3])
        : "r"(saddr));
}

// ---------------------------------------------------------------------------
// K4: mlp (unchanged from R7 — pipelined double buffer, 4 reps/block)
// ---------------------------------------------------------------------------
#define MLP_REPS 4

__global__ void __launch_bounds__(256) mlp_kernel() {
    __shared__ __align__(16) __nv_bfloat16 Whi[128 * 64];
    __shared__ __align__(16) __nv_bfloat16 Bhs[2][64 * 64];
    __shared__ __align__(16) __nv_bfloat16 Bls[2][64 * 64];

    int t = threadIdx.x;
    int lane = t & 31, w = t >> 5;
    int combo = blockIdx.y;
    int j = combo % 3;
    int bs = combo / 3;
    int b = bs >> 3, s = bs & 7;
    int g = s - 1 + j;
    g = g < 0 ? 0 : (g > 7 ? 7 : g);

    {
        const uint4* gh = (const uint4*)g_Ws1hi;
        uint4* sh = (uint4*)Whi;
        for (int i = t; i < 1024; i += 256) {
            int r = i >> 3, c = i & 7;
            sh[(r << 3) + (c ^ (r & 7))] = gh[i];
        }
    }
    __syncthreads();

    unsigned sWhi = (unsigned)__cvta_generic_to_shared(Whi);
    unsigned sBh0 = (unsigned)__cvta_generic_to_shared(Bhs[0]);
    unsigned sBl0 = (unsigned)__cvta_generic_to_shared(Bls[0]);

    unsigned ahi[4][4], alo[4][4];
    {
        int r = w * 16 + (lane & 15);
#pragma unroll
        for (int ks = 0; ks < 4; ks++) {
            int chunk = ks * 2 + (lane >> 4);
            ldsm4(ahi[ks], sWhi + r * 128 + ((chunk ^ (r & 7)) << 4));
            uint4 fl = ((const uint4*)g_WsFragLo)[(w * 4 + ks) * 32 + lane];
            alo[ks][0] = fl.x; alo[ks][1] = fl.y; alo[ks][2] = fl.z; alo[ks][3] = fl.w;
        }
    }

    int col = t & 63;
    int kq = t >> 6;
    int brow_base = (lane & 7) + ((lane & 16) >> 1);
    int bksel = (lane >> 3) & 1;

    const float4* Pbase = (const float4*)(g_P + (size_t)(b * 8 + g) * Nn * 64);
    const float4* Abase = (const float4*)(g_A + (size_t)bs * Mn * 64);
    const int* idxbase = g_idx + (size_t)combo * Mn * Kn;

    float4 pf_p[4], pf_a[4];

    {
        int gcol = blockIdx.x * MLP_REPS * 64 + col;
        int m = gcol >> 5, knb = gcol & 31;
        int n = idxbase[m * Kn + knb];
        const float4* Prow = Pbase + (size_t)n * 16;
        const float4* Arow = Abase + (size_t)m * 16;
#pragma unroll
        for (int q = 0; q < 4; q++) { pf_p[q] = Prow[kq * 4 + q]; pf_a[q] = Arow[kq * 4 + q]; }
    }
    {
        char* bh = (char*)Bhs[0];
        char* bl = (char*)Bls[0];
#pragma unroll
        for (int q = 0; q < 4; q++) {
            float h0 = fmaxf(pf_p[q].x - pf_a[q].x, 0.f);
            float h1 = fmaxf(pf_p[q].y - pf_a[q].y, 0.f);
            float h2 = fmaxf(pf_p[q].z - pf_a[q].z, 0.f);
            float h3 = fmaxf(pf_p[q].w - pf_a[q].w, 0.f);
            __nv_bfloat162 hiA, hiB, loA, loB;
            hiA.x = __float2bfloat16_rn(h0); hiA.y = __float2bfloat16_rn(h1);
            hiB.x = __float2bfloat16_rn(h2); hiB.y = __float2bfloat16_rn(h3);
            loA.x = __float2bfloat16_rn(h0 - __bfloat162float(hiA.x));
            loA.y = __float2bfloat16_rn(h1 - __bfloat162float(hiA.y));
            loB.x = __float2bfloat16_rn(h2 - __bfloat162float(hiB.x));
            loB.y = __float2bfloat16_rn(h3 - __bfloat162float(hiB.y));
            int k0 = kq * 16 + q * 4;
            int chunk = k0 >> 3;
            int off = col * 128 + ((chunk ^ (col & 7)) << 4) + ((k0 & 7) << 1);
            uint2 vh, vl;
            vh.x = *(unsigned*)&hiA; vh.y = *(unsigned*)&hiB;
            vl.x = *(unsigned*)&loA; vl.y = *(unsigned*)&loB;
            *(uint2*)(bh + off) = vh;
            *(uint2*)(bl + off) = vl;
        }
    }
    __syncthreads();

#pragma unroll
    for (int rep = 0; rep < MLP_REPS; rep++) {
        int buf = rep & 1;
        if (rep + 1 < MLP_REPS) {
            int gcol = (blockIdx.x * MLP_REPS + rep + 1) * 64 + col;
            int m = gcol >> 5, knb = gcol & 31;
            int n = idxbase[m * Kn + knb];
            const float4* Prow = Pbase + (size_t)n * 16;
            const float4* Arow = Abase + (size_t)m * 16;
#pragma unroll
            for (int q = 0; q < 4; q++) { pf_p[q] = Prow[kq * 4 + q]; pf_a[q] = Arow[kq * 4 + q]; }
        }

        float acc[8][4];
#pragma unroll
        for (int nt = 0; nt < 8; nt++)
#pragma unroll
            for (int i = 0; i < 4; i++) acc[nt][i] = 0.f;

        unsigned sBh = sBh0 + buf * 8192;
        unsigned sBl = sBl0 + buf * 8192;
#pragma unroll
        for (int ks = 0; ks < 4; ks++) {
#pragma unroll
            for (int p = 0; p < 4; p++) {
                int r = p * 16 + brow_base;
                int chunk = ks * 2 + bksel;
                unsigned off = r * 128 + ((chunk ^ (r & 7)) << 4);
                unsigned tmp[4];
                ldsm4(tmp, sBh + off);
                unsigned bh0 = tmp[0], bh1 = tmp[1];
                unsigned th2 = tmp[2], th3 = tmp[3];
                ldsm4(tmp, sBl + off);
                mma_bf16(acc[2 * p],     ahi[ks], bh0, bh1);
                mma_bf16(acc[2 * p],     ahi[ks], tmp[0], tmp[1]);
                mma_bf16(acc[2 * p],     alo[ks], bh0, bh1);
                mma_bf16(acc[2 * p + 1], ahi[ks], th2, th3);
                mma_bf16(acc[2 * p + 1], ahi[ks], tmp[2], tmp[3]);
                mma_bf16(acc[2 * p + 1], alo[ks], th2, th3);
            }
        }

        if (rep + 1 < MLP_REPS) {
            char* bh = (char*)Bhs[buf ^ 1];
            char* bl = (char*)Bls[buf ^ 1];
#pragma unroll
            for (int q = 0; q < 4; q++) {
                float h0 = fmaxf(pf_p[q].x - pf_a[q].x, 0.f);
                float h1 = fmaxf(pf_p[q].y - pf_a[q].y, 0.f);
                float h2 = fmaxf(pf_p[q].z - pf_a[q].z, 0.f);
                float h3 = fmaxf(pf_p[q].w - pf_a[q].w, 0.f);
                __nv_bfloat162 hiA, hiB, loA, loB;
                hiA.x = __float2bfloat16_rn(h0); hiA.y = __float2bfloat16_rn(h1);
                hiB.x = __float2bfloat16_rn(h2); hiB.y = __float2bfloat16_rn(h3);
                loA.x = __float2bfloat16_rn(h0 - __bfloat162float(hiA.x));
                loA.y = __float2bfloat16_rn(h1 - __bfloat162float(hiA.y));
                loB.x = __float2bfloat16_rn(h2 - __bfloat162float(hiB.x));
                loB.y = __float2bfloat16_rn(h3 - __bfloat162float(hiB.y));
                int k0 = kq * 16 + q * 4;
                int chunk = k0 >> 3;
                int off = col * 128 + ((chunk ^ (col & 7)) << 4) + ((k0 & 7) << 1);
                uint2 vh, vl;
                vh.x = *(unsigned*)&hiA; vh.y = *(unsigned*)&hiB;
                vl.x = *(unsigned*)&loA; vl.y = *(unsigned*)&loB;
                *(uint2*)(bh + off) = vh;
                *(uint2*)(bl + off) = vl;
            }
        }

        int mbase = (blockIdx.x * MLP_REPS + rep) * 2;
        int grp = lane >> 2;
#pragma unroll
        for (int a = 0; a < 2; a++) {
            float m0 = -1e30f, m1 = -1e30f;
#pragma unroll
            for (int nt = a * 4; nt < a * 4 + 4; nt++) {
                m0 = fmaxf(m0, fmaxf(acc[nt][0], acc[nt][1]));
                m1 = fmaxf(m1, fmaxf(acc[nt][2], acc[nt][3]));
            }
            m0 = fmaxf(m0, __shfl_xor_sync(0xffffffffu, m0, 1));
            m0 = fmaxf(m0, __shfl_xor_sync(0xffffffffu, m0, 2));
            m1 = fmaxf(m1, __shfl_xor_sync(0xffffffffu, m1, 1));
            m1 = fmaxf(m1, __shfl_xor_sync(0xffffffffu, m1, 2));
            if ((lane & 3) == 0) {
                float* o = g_hmax + ((size_t)combo * Mn + mbase + a) * 128 + w * 16 + grp;
                o[0] = fmaxf(m0, 0.f);
                o[8] = fmaxf(m1, 0.f);
            }
        }
        __syncthreads();
    }
}

// ---------------------------------------------------------------------------
// K5: wt on tensor cores. out[bs][o][m] = sum_j relu(Wt[j] @ hmax[bs][j]).
// Block: 32 anchors (cols) x 256 rows, K=128. grid (64, 32). 8 warps,
// warp w owns rows [32w, 32w+32) (2 mtiles). B (hmax) hi/lo in smem,
// double-buffered across j; A (Wt) frags streamed from pre-packed gmem.
// ---------------------------------------------------------------------------
__device__ __forceinline__ void wt_produce(char* bh, char* bl, const float4* pf,
                                           int col, int kq) {
#pragma unroll
    for (int q = 0; q < 4; q++) {
        float4 v = pf[q];
        __nv_bfloat162 hiA, hiB, loA, loB;
        hiA.x = __float2bfloat16_rn(v.x); hiA.y = __float2bfloat16_rn(v.y);
        hiB.x = __float2bfloat16_rn(v.z); hiB.y = __float2bfloat16_rn(v.w);
        loA.x = __float2bfloat16_rn(v.x - __bfloat162float(hiA.x));
        loA.y = __float2bfloat16_rn(v.y - __bfloat162float(hiA.y));
        loB.x = __float2bfloat16_rn(v.z - __bfloat162float(hiB.x));
        loB.y = __float2bfloat16_rn(v.w - __bfloat162float(hiB.y));
        int k0 = kq * 16 + q * 4;
        int chunk = k0 >> 3;
        int off = col * 256 + ((chunk ^ (col & 7)) << 4) + ((k0 & 7) << 1);
        uint2 vh, vl;
        vh.x = *(unsigned*)&hiA; vh.y = *(unsigned*)&hiB;
        vl.x = *(unsigned*)&loA; vl.y = *(unsigned*)&loB;
        *(uint2*)(bh + off) = vh;
        *(uint2*)(bl + off) = vl;
    }
}

__global__ void __launch_bounds__(256) wt_kernel(float* __restrict__ outf) {
    __shared__ __align__(16) __nv_bfloat16 Bh[2][32 * 128];  // 2x8KB [col][k] swizzled
    __shared__ __align__(16) __nv_bfloat16 Bl[2][32 * 128];  // 2x8KB

    int t = threadIdx.x;
    int lane = t & 31, w = t >> 5;
    int bs = blockIdx.y;
    int mbase = blockIdx.x * 32;

    int col = t >> 3;      // 0..31
    int kq = t & 7;        // k range [16kq, 16kq+16)
    int brow_base = (lane & 7) + ((lane & 16) >> 1);
    int bksel = (lane >> 3) & 1;

    unsigned sBh0 = (unsigned)__cvta_generic_to_shared(Bh[0]);
    unsigned sBl0 = (unsigned)__cvta_generic_to_shared(Bl[0]);

    float4 pf[4];
    {
        const float4* src = (const float4*)(g_hmax +
            (((size_t)(bs * 3 + 0)) * Mn + mbase + col) * 128 + kq * 16);
#pragma unroll
        for (int q = 0; q < 4; q++) pf[q] = src[q];
    }
    wt_produce((char*)Bh[0], (char*)Bl[0], pf, col, kq);
    __syncthreads();

    float tot[2][4][4];
#pragma unroll
    for (int mt = 0; mt < 2; mt++)
#pragma unroll
        for (int nt = 0; nt < 4; nt++)
#pragma unroll
            for (int i = 0; i < 4; i++) tot[mt][nt][i] = 0.f;

    const uint4* fragHi = (const uint4*)g_WtFragHi;
    const uint4* fragLo = (const uint4*)g_WtFragLo;

#pragma unroll
    for (int j = 0; j < 3; j++) {
        if (j < 2) {
            const float4* src = (const float4*)(g_hmax +
                (((size_t)(bs * 3 + j + 1)) * Mn + mbase + col) * 128 + kq * 16);
#pragma unroll
            for (int q = 0; q < 4; q++) pf[q] = src[q];
        }

        float acc[2][4][4];
#pragma unroll
        for (int mt = 0; mt < 2; mt++)
#pragma unroll
            for (int nt = 0; nt < 4; nt++)
#pragma unroll
                for (int i = 0; i < 4; i++) acc[mt][nt][i] = 0.f;

        unsigned sBhj = sBh0 + (j & 1) * 8192;
        unsigned sBlj = sBl0 + (j & 1) * 8192;

#pragma unroll
        for (int ks = 0; ks < 8; ks++) {
            uint4 fh0 = fragHi[((j * 16 + w * 2 + 0) * 8 + ks) * 32 + lane];
            uint4 fl0 = fragLo[((j * 16 + w * 2 + 0) * 8 + ks) * 32 + lane];
            uint4 fh1 = fragHi[((j * 16 + w * 2 + 1) * 8 + ks) * 32 + lane];
            uint4 fl1 = fragLo[((j * 16 + w * 2 + 1) * 8 + ks) * 32 + lane];
            unsigned ah0[4] = {fh0.x, fh0.y, fh0.z, fh0.w};
            unsigned al0[4] = {fl0.x, fl0.y, fl0.z, fl0.w};
            unsigned ah1[4] = {fh1.x, fh1.y, fh1.z, fh1.w};
            unsigned al1[4] = {fl1.x, fl1.y, fl1.z, fl1.w};
            int chunk = ks * 2 + bksel;
#pragma unroll
            for (int p = 0; p < 2; p++) {
                int r = p * 16 + brow_base;
                unsigned off = r * 256 + ((chunk ^ (r & 7)) << 4);
                unsigned hh[4], ll[4];
                ldsm4(hh, sBhj + off);
                ldsm4(ll, sBlj + off);
                mma_bf16(acc[0][2 * p],     ah0, hh[0], hh[1]);
                mma_bf16(acc[0][2 * p],     ah0, ll[0], ll[1]);
                mma_bf16(acc[0][2 * p],     al0, hh[0], hh[1]);
                mma_bf16(acc[0][2 * p + 1], ah0, hh[2], hh[3]);
                mma_bf16(acc[0][2 * p + 1], ah0, ll[2], ll[3]);
                mma_bf16(acc[0][2 * p + 1], al0, hh[2], hh[3]);
                mma_bf16(acc[1][2 * p],     ah1, hh[0], hh[1]);
                mma_bf16(acc[1][2 * p],     ah1, ll[0], ll[1]);
                mma_bf16(acc[1][2 * p],     al1, hh[0], hh[1]);
                mma_bf16(acc[1][2 * p + 1], ah1, hh[2], hh[3]);
                mma_bf16(acc[1][2 * p + 1], ah1, ll[2], ll[3]);
                mma_bf16(acc[1][2 * p + 1], al1, hh[2], hh[3]);
            }
        }

        if (j < 2)
            wt_produce((char*)Bh[(j + 1) & 1], (char*)Bl[(j + 1) & 1], pf, col, kq);

#pragma unroll
        for (int mt = 0; mt < 2; mt++)
#pragma unroll
            for (int nt = 0; nt < 4; nt++)
#pragma unroll
                for (int i = 0; i < 4; i++)
                    tot[mt][nt][i] += fmaxf(acc[mt][nt][i], 0.f);
        __syncthreads();
    }

    // store: row = 32w + 16mt + (lane>>2) (+8), col = mbase + 8nt + (lane&3)*2
#pragma unroll
    for (int mt = 0; mt < 2; mt++) {
        int row = w * 32 + mt * 16 + (lane >> 2);
#pragma unroll
        for (int nt = 0; nt < 4; nt++) {
            int c = mbase + nt * 8 + (lane & 3) * 2;
            float2 v0; v0.x = tot[mt][nt][0]; v0.y = tot[mt][nt][1];
            float2 v1; v1.x = tot[mt][nt][2]; v1.y = tot[mt][nt][3];
            *(float2*)&outf[((size_t)bs * 256 + row) * Mn + c] = v0;
            *(float2*)&outf[((size_t)bs * 256 + row + 8) * Mn + c] = v1;
        }
    }
}

// ---------------------------------------------------------------------------
extern "C" void kernel_launch(void* const* d_in, const int* in_sizes, int n_in,
                              void* d_out, int out_size) {
    const float* xyzs = (const float*)d_in[0];
    const float* feats = (const float*)d_in[1];
    const float* Ws0 = (const float*)d_in[2];
    const float* Ws1 = (const float*)d_in[3];
    const float* Wt = (const float*)d_in[4];
    float* out = (float*)d_out;

    const int XYZ_TOTAL = Bn * Sn * Mn * 3;  // 196608

    wsprep<<<32, 256>>>(Ws1);                                        // 1
    wtfrag_hi<<<192, 256>>>(Wt);                                     // 2
    wtfrag_lo<<<192, 256>>>(Wt);                                     // 3
    fps_kernel<<<Bn * Sn, 256>>>(xyzs, out);                         // 4 (profiled)
    compute_PA<<<768, 256>>>(xyzs, feats, Ws0);                      // 5
    ball_query_kernel<<<dim3(Mn / 8, Bn * Sn * Jn), 256>>>(xyzs);    // 6
    mlp_kernel<<<dim3(Mn * Kn / (64 * MLP_REPS), Bn * Sn * Jn), 256>>>();  // 7
    wt_kernel<<<dim3(Mn / 32, Bn * Sn), 256>>>(out + XYZ_TOTAL);     // 8
}

// round 9
// speedup vs baseline: 2.0025x; 1.0848x over previous
#include <cuda_runtime.h>
#include <cuda_bf16.h>

// Problem constants
#define Bn 4
#define Ln 8
#define Nn 4096
#define Mn 2048
#define Kn 32
#define Sn 8
#define Jn 3

// Staging buffers (device globals; no runtime allocation)
__device__ float g_anchors[Bn * Sn * Mn * 3];
__device__ float g_P[Bn * 8 * Nn * 64];
__device__ float g_A[Bn * Sn * Mn * 64];
__device__ int   g_idx[Bn * Sn * Jn * Mn * Kn];
__device__ float g_hmax[Bn * Sn * Jn * Mn * 128];        // [combo][m][r]
__device__ __nv_bfloat16 g_Ws1hi[128 * 64];              // Ws1 hi, [r][k] row-major
__device__ unsigned g_WsFragLo[8 * 4 * 32 * 4];          // Ws1 lo in mma A-frag layout
__device__ unsigned g_WtFragHi[3 * 16 * 8 * 32 * 4];     // Wt hi in mma A-frag layout
__device__ unsigned g_WtFragLo[3 * 16 * 8 * 32 * 4];     // Wt lo

// ---------------------------------------------------------------------------
// K1: FPS (unchanged from R8 — known good, near serial floor).
// ---------------------------------------------------------------------------
__global__ void __launch_bounds__(256) fps_kernel(const float* __restrict__ xyzs,
                                                  float* __restrict__ out_xyz) {
    int bs = blockIdx.x;
    const float* xyz = xyzs + (size_t)bs * Nn * 3;
    __shared__ unsigned long long skey[2][8];

    int t = threadIdx.x;
    int lane = t & 31, wid = t >> 5;

    float px[16], py[16], pz[16], pd[16];
#pragma unroll
    for (int i = 0; i < 16; i++) {
        int p = t + i * 256;
        px[i] = xyz[3 * p]; py[i] = xyz[3 * p + 1]; pz[i] = xyz[3 * p + 2];
        pd[i] = 1e10f;
    }
    float cx = xyz[0], cy = xyz[1], cz = xyz[2];

    float* oanc = g_anchors + (size_t)bs * Mn * 3;
    float* oxyz = out_xyz + (size_t)bs * Mn * 3;

    for (int m = 0; m < Mn; m++) {
        if (t == 0) {
            oanc[3 * m] = cx; oanc[3 * m + 1] = cy; oanc[3 * m + 2] = cz;
            oxyz[3 * m] = cx; oxyz[3 * m + 1] = cy; oxyz[3 * m + 2] = cz;
        }
        unsigned long long key = 0;
#pragma unroll
        for (int i = 0; i < 16; i++) {
            float dx = __fsub_rn(px[i], cx);
            float dy = __fsub_rn(py[i], cy);
            float dz = __fsub_rn(pz[i], cz);
            float d = __fadd_rn(__fadd_rn(__fmul_rn(dx, dx), __fmul_rn(dy, dy)),
                                __fmul_rn(dz, dz));
            float nd = fminf(pd[i], d);
            pd[i] = nd;
            unsigned long long k =
                ((unsigned long long)__float_as_uint(nd) << 32) |
                (unsigned)(0xFFFFFFFFu - (unsigned)(t + i * 256));
            key = (k > key) ? k : key;
        }
#pragma unroll
        for (int off = 16; off > 0; off >>= 1) {
            unsigned long long k2 = __shfl_xor_sync(0xffffffffu, key, off);
            key = (k2 > key) ? k2 : key;
        }
        if (lane == 0) skey[m & 1][wid] = key;
        __syncthreads();
        unsigned long long kb = skey[m & 1][0];
#pragma unroll
        for (int wq = 1; wq < 8; wq++) {
            unsigned long long k2 = skey[m & 1][wq];
            kb = (k2 > kb) ? k2 : kb;
        }
        int widx = (int)(0xFFFFFFFFu - (unsigned)kb);
        cx = xyz[3 * widx]; cy = xyz[3 * widx + 1]; cz = xyz[3 * widx + 2];
    }
}

// ---------------------------------------------------------------------------
// Weight prep kernels (unchanged)
// ---------------------------------------------------------------------------
__global__ void __launch_bounds__(256) wsprep(const float* __restrict__ Ws1) {
    int t = blockIdx.x * 256 + threadIdx.x;
    if (t < 128 * 64) {
        g_Ws1hi[t] = __float2bfloat16_rn(Ws1[t]);
    }
    if (t < 8 * 4 * 32 * 4) {
        int q = t & 3, lane = (t >> 2) & 31, ks = (t >> 7) & 3, w8 = t >> 9;
        int row = w8 * 16 + (lane >> 2) + (q & 1) * 8;
        int k = ks * 16 + (lane & 3) * 2 + ((q >> 1) & 1) * 8;
        float e0 = Ws1[row * 64 + k];
        float e1 = Ws1[row * 64 + k + 1];
        __nv_bfloat16 h0 = __float2bfloat16_rn(e0);
        __nv_bfloat16 h1 = __float2bfloat16_rn(e1);
        __nv_bfloat16 l0 = __float2bfloat16_rn(e0 - __bfloat162float(h0));
        __nv_bfloat16 l1 = __float2bfloat16_rn(e1 - __bfloat162float(h1));
        unsigned ul0 = *(unsigned short*)&l0, ul1 = *(unsigned short*)&l1;
        g_WsFragLo[t] = (ul1 << 16) | ul0;
    }
}

__global__ void __launch_bounds__(256) wtfrag_hi(const float* __restrict__ Wt) {
    int i = blockIdx.x * 256 + threadIdx.x;
    int q = i & 3, lane = (i >> 2) & 31, ks = (i >> 7) & 7, rb = (i >> 10) & 15, j = i >> 14;
    int row = rb * 16 + (lane >> 2) + (q & 1) * 8;
    int k = ks * 16 + (lane & 3) * 2 + ((q >> 1) & 1) * 8;
    float e0 = Wt[(j * 256 + row) * 128 + k];
    float e1 = Wt[(j * 256 + row) * 128 + k + 1];
    __nv_bfloat16 h0 = __float2bfloat16_rn(e0);
    __nv_bfloat16 h1 = __float2bfloat16_rn(e1);
    unsigned u0 = *(unsigned short*)&h0, u1 = *(unsigned short*)&h1;
    g_WtFragHi[i] = (u1 << 16) | u0;
}

__global__ void __launch_bounds__(256) wtfrag_lo(const float* __restrict__ Wt) {
    int i = blockIdx.x * 256 + threadIdx.x;
    int q = i & 3, lane = (i >> 2) & 31, ks = (i >> 7) & 7, rb = (i >> 10) & 15, j = i >> 14;
    int row = rb * 16 + (lane >> 2) + (q & 1) * 8;
    int k = ks * 16 + (lane & 3) * 2 + ((q >> 1) & 1) * 8;
    float e0 = Wt[(j * 256 + row) * 128 + k];
    float e1 = Wt[(j * 256 + row) * 128 + k + 1];
    __nv_bfloat16 h0 = __float2bfloat16_rn(e0);
    __nv_bfloat16 h1 = __float2bfloat16_rn(e1);
    __nv_bfloat16 l0 = __float2bfloat16_rn(e0 - __bfloat162float(h0));
    __nv_bfloat16 l1 = __float2bfloat16_rn(e1 - __bfloat162float(h1));
    unsigned u0 = *(unsigned short*)&l0, u1 = *(unsigned short*)&l1;
    g_WtFragLo[i] = (u1 << 16) | u0;
}

// ---------------------------------------------------------------------------
// K2: P (blocks [0,512)) + A (blocks [512,768)) projections (unchanged).
// ---------------------------------------------------------------------------
__global__ void __launch_bounds__(256) compute_PA(const float* __restrict__ xyzs,
                                                  const float* __restrict__ feats,
                                                  const float* __restrict__ Ws0) {
    int t = threadIdx.x;
    if (blockIdx.x < 512) {
        __shared__ float w[64 * 6];
        for (int i = t; i < 64 * 6; i += 256) w[i] = Ws0[i];
        __syncthreads();

        int gp = blockIdx.x * 256 + t;
        int n = gp & (Nn - 1);
        int bf = gp >> 12;
        const float* p = xyzs + (size_t)gp * 3;
        float x = p[0], y = p[1], z = p[2];
        const float* f = feats + (size_t)bf * 3 * Nn + n;
        float f0 = f[0], f1 = f[Nn], f2 = f[2 * Nn];
        float4* o = (float4*)(g_P + (size_t)gp * 64);
#pragma unroll
        for (int oo = 0; oo < 64; oo += 4) {
            float4 r;
            const float* w0 = w + oo * 6;
            r.x = w0[0] * x + w0[1] * y + w0[2] * z + w0[3] * f0 + w0[4] * f1 + w0[5] * f2;
            r.y = w0[6] * x + w0[7] * y + w0[8] * z + w0[9] * f0 + w0[10] * f1 + w0[11] * f2;
            r.z = w0[12] * x + w0[13] * y + w0[14] * z + w0[15] * f0 + w0[16] * f1 + w0[17] * f2;
            r.w = w0[18] * x + w0[19] * y + w0[20] * z + w0[21] * f0 + w0[22] * f1 + w0[23] * f2;
            o[oo >> 2] = r;
        }
    } else {
        __shared__ float w[64 * 3];
        for (int i = t; i < 64 * 3; i += 256) {
            int o = i / 3, c = i % 3;
            w[i] = Ws0[o * 6 + c];
        }
        __syncthreads();
        int ga = (blockIdx.x - 512) * 256 + t;
        const float* a = g_anchors + (size_t)ga * 3;
        float x = a[0], y = a[1], z = a[2];
        float4* o = (float4*)(g_A + (size_t)ga * 64);
#pragma unroll
        for (int oo = 0; oo < 64; oo += 4) {
            float4 r;
            const float* w0 = w + oo * 3;
            r.x = w0[0] * x + w0[1] * y + w0[2] * z;
            r.y = w0[3] * x + w0[4] * y + w0[5] * z;
            r.z = w0[6] * x + w0[7] * y + w0[8] * z;
            r.w = w0[9] * x + w0[10] * y + w0[11] * z;
            o[oo >> 2] = r;
        }
    }
}

// ---------------------------------------------------------------------------
// K3: ball query — 2 points per lane per iteration (64 points/warp-iter).
// Aligned float2 loads; exact first-32-ascending semantics preserved:
// position = found + popc(m0&lt) + popc(m1&lt) (+p0 for the s=1 slot),
// first = min over interleaved (lane,s) candidates. No-FMA distance math.
// ---------------------------------------------------------------------------
__global__ void __launch_bounds__(256) ball_query_kernel(const float* __restrict__ xyzs) {
    int combo = blockIdx.y;
    int j = combo % 3;
    int bs = combo / 3;
    int b = bs >> 3, s = bs & 7;
    int g = s - 1 + j;
    g = g < 0 ? 0 : (g > 7 ? 7 : g);
    int wid = threadIdx.x >> 5, lane = threadIdx.x & 31;
    int m = blockIdx.x * 8 + wid;

    const float* pts = xyzs + (size_t)(b * 8 + g) * Nn * 3;
    const float* anc = g_anchors + ((size_t)bs * Mn + m) * 3;
    float ax = anc[0], ay = anc[1], az = anc[2];
    int* out = g_idx + ((size_t)combo * Mn + m) * Kn;

    int found = 0, first = -1;
    unsigned lt = (1u << lane) - 1u;
    for (int base = 0; base < Nn && found < Kn; base += 64) {
        int n0 = base + 2 * lane;
        const float* pp = pts + 3 * n0;
        float2 a0 = *(const float2*)(pp);      // x0 y0
        float2 a1 = *(const float2*)(pp + 2);  // z0 x1
        float2 a2 = *(const float2*)(pp + 4);  // y1 z1

        float dx0 = __fsub_rn(a0.x, ax);
        float dy0 = __fsub_rn(a0.y, ay);
        float dz0 = __fsub_rn(a1.x, az);
        float d0 = __fadd_rn(__fadd_rn(__fmul_rn(dx0, dx0), __fmul_rn(dy0, dy0)),
                             __fmul_rn(dz0, dz0));
        float dx1 = __fsub_rn(a1.y, ax);
        float dy1 = __fsub_rn(a2.x, ay);
        float dz1 = __fsub_rn(a2.y, az);
        float d1 = __fadd_rn(__fadd_rn(__fmul_rn(dx1, dx1), __fmul_rn(dy1, dy1)),
                             __fmul_rn(dz1, dz1));

        bool p0 = d0 < 0.25f;
        bool p1 = d1 < 0.25f;
        unsigned m0 = __ballot_sync(0xffffffffu, p0);
        unsigned m1 = __ballot_sync(0xffffffffu, p1);
        if (first < 0 && (m0 | m1)) {
            int c0 = m0 ? 2 * (__ffs(m0) - 1) : 0x7fffffff;
            int c1 = m1 ? 2 * (__ffs(m1) - 1) + 1 : 0x7fffffff;
            first = base + (c0 < c1 ? c0 : c1);
        }
        int before = found + __popc(m0 & lt) + __popc(m1 & lt);
        if (p0 && before < Kn) out[before] = n0;
        int pos1 = before + (p0 ? 1 : 0);
        if (p1 && pos1 < Kn) out[pos1] = n0 + 1;
        found += __popc(m0) + __popc(m1);
    }
    if (found < Kn) {
        int pad = first < 0 ? 0 : first;
        for (int p = found + lane; p < Kn; p += 32) out[p] = pad;
    }
}

// ---------------------------------------------------------------------------
// mma / ldsm helpers
// ---------------------------------------------------------------------------
__device__ __forceinline__ void mma_bf16(float c[4], const unsigned a[4],
                                         unsigned b0, unsigned b1) {
    asm volatile(
        "mma.sync.aligned.m16n8k16.row.col.f32.bf16.bf16.f32 "
        "{%0,%1,%2,%3}, {%4,%5,%6,%7}, {%8,%9}, {%0,%1,%2,%3};"
        : "+f"(c[0]), "+f"(c[1]), "+f"(c[2]), "+f"(c[3])
        : "r"(a[0]), "r"(a[1]), "r"(a[2]), "r"(a[3]), "r"(b0), "r"(b1));
}

__device__ __forceinline__ void ldsm4(unsigned r[4], unsigned saddr) {
    asm volatile(
        "ldmatrix.sync.aligned.m8n8.x4.shared.b16 {%0,%1,%2,%3}, [%4];"
        : "=r"(r[0]), "=r"(r[1]), "=r"(r[2]), "=r"(r[3])
        : "r"(saddr));
}

// ---------------------------------------------------------------------------
// K4: mlp (R7 structure, MLP_REPS=8 with dynamic rep loop)
// ---------------------------------------------------------------------------
#define MLP_REPS 8

__global__ void __launch_bounds__(256) mlp_kernel() {
    __shared__ __align__(16) __nv_bfloat16 Whi[128 * 64];
    __shared__ __align__(16) __nv_bfloat16 Bhs[2][64 * 64];
    __shared__ __align__(16) __nv_bfloat16 Bls[2][64 * 64];

    int t = threadIdx.x;
    int lane = t & 31, w = t >> 5;
    int combo = blockIdx.y;
    int j = combo % 3;
    int bs = combo / 3;
    int b = bs >> 3, s = bs & 7;
    int g = s - 1 + j;
    g = g < 0 ? 0 : (g > 7 ? 7 : g);

    {
        const uint4* gh = (const uint4*)g_Ws1hi;
        uint4* sh = (uint4*)Whi;
        for (int i = t; i < 1024; i += 256) {
            int r = i >> 3, c = i & 7;
            sh[(r << 3) + (c ^ (r & 7))] = gh[i];
        }
    }
    __syncthreads();

    unsigned sWhi = (unsigned)__cvta_generic_to_shared(Whi);
    unsigned sBh0 = (unsigned)__cvta_generic_to_shared(Bhs[0]);
    unsigned sBl0 = (unsigned)__cvta_generic_to_shared(Bls[0]);

    unsigned ahi[4][4], alo[4][4];
    {
        int r = w * 16 + (lane & 15);
#pragma unroll
        for (int ks = 0; ks < 4; ks++) {
            int chunk = ks * 2 + (lane >> 4);
            ldsm4(ahi[ks], sWhi + r * 128 + ((chunk ^ (r & 7)) << 4));
            uint4 fl = ((const uint4*)g_WsFragLo)[(w * 4 + ks) * 32 + lane];
            alo[ks][0] = fl.x; alo[ks][1] = fl.y; alo[ks][2] = fl.z; alo[ks][3] = fl.w;
        }
    }

    int col = t & 63;
    int kq = t >> 6;
    int brow_base = (lane & 7) + ((lane & 16) >> 1);
    int bksel = (lane >> 3) & 1;

    const float4* Pbase = (const float4*)(g_P + (size_t)(b * 8 + g) * Nn * 64);
    const float4* Abase = (const float4*)(g_A + (size_t)bs * Mn * 64);
    const int* idxbase = g_idx + (size_t)combo * Mn * Kn;

    float4 pf_p[4], pf_a[4];

    {
        int gcol = blockIdx.x * MLP_REPS * 64 + col;
        int m = gcol >> 5, knb = gcol & 31;
        int n = idxbase[m * Kn + knb];
        const float4* Prow = Pbase + (size_t)n * 16;
        const float4* Arow = Abase + (size_t)m * 16;
#pragma unroll
        for (int q = 0; q < 4; q++) { pf_p[q] = Prow[kq * 4 + q]; pf_a[q] = Arow[kq * 4 + q]; }
    }
    {
        char* bh = (char*)Bhs[0];
        char* bl = (char*)Bls[0];
#pragma unroll
        for (int q = 0; q < 4; q++) {
            float h0 = fmaxf(pf_p[q].x - pf_a[q].x, 0.f);
            float h1 = fmaxf(pf_p[q].y - pf_a[q].y, 0.f);
            float h2 = fmaxf(pf_p[q].z - pf_a[q].z, 0.f);
            float h3 = fmaxf(pf_p[q].w - pf_a[q].w, 0.f);
            __nv_bfloat162 hiA, hiB, loA, loB;
            hiA.x = __float2bfloat16_rn(h0); hiA.y = __float2bfloat16_rn(h1);
            hiB.x = __float2bfloat16_rn(h2); hiB.y = __float2bfloat16_rn(h3);
            loA.x = __float2bfloat16_rn(h0 - __bfloat162float(hiA.x));
            loA.y = __float2bfloat16_rn(h1 - __bfloat162float(hiA.y));
            loB.x = __float2bfloat16_rn(h2 - __bfloat162float(hiB.x));
            loB.y = __float2bfloat16_rn(h3 - __bfloat162float(hiB.y));
            int k0 = kq * 16 + q * 4;
            int chunk = k0 >> 3;
            int off = col * 128 + ((chunk ^ (col & 7)) << 4) + ((k0 & 7) << 1);
            uint2 vh, vl;
            vh.x = *(unsigned*)&hiA; vh.y = *(unsigned*)&hiB;
            vl.x = *(unsigned*)&loA; vl.y = *(unsigned*)&loB;
            *(uint2*)(bh + off) = vh;
            *(uint2*)(bl + off) = vl;
        }
    }
    __syncthreads();

    for (int rep = 0; rep < MLP_REPS; rep++) {
        int buf = rep & 1;
        if (rep + 1 < MLP_REPS) {
            int gcol = (blockIdx.x * MLP_REPS + rep + 1) * 64 + col;
            int m = gcol >> 5, knb = gcol & 31;
            int n = idxbase[m * Kn + knb];
            const float4* Prow = Pbase + (size_t)n * 16;
            const float4* Arow = Abase + (size_t)m * 16;
#pragma unroll
            for (int q = 0; q < 4; q++) { pf_p[q] = Prow[kq * 4 + q]; pf_a[q] = Arow[kq * 4 + q]; }
        }

        float acc[8][4];
#pragma unroll
        for (int nt = 0; nt < 8; nt++)
#pragma unroll
            for (int i = 0; i < 4; i++) acc[nt][i] = 0.f;

        unsigned sBh = sBh0 + buf * 8192;
        unsigned sBl = sBl0 + buf * 8192;
#pragma unroll
        for (int ks = 0; ks < 4; ks++) {
#pragma unroll
            for (int p = 0; p < 4; p++) {
                int r = p * 16 + brow_base;
                int chunk = ks * 2 + bksel;
                unsigned off = r * 128 + ((chunk ^ (r & 7)) << 4);
                unsigned tmp[4];
                ldsm4(tmp, sBh + off);
                unsigned bh0 = tmp[0], bh1 = tmp[1];
                unsigned th2 = tmp[2], th3 = tmp[3];
                ldsm4(tmp, sBl + off);
                mma_bf16(acc[2 * p],     ahi[ks], bh0, bh1);
                mma_bf16(acc[2 * p],     ahi[ks], tmp[0], tmp[1]);
                mma_bf16(acc[2 * p],     alo[ks], bh0, bh1);
                mma_bf16(acc[2 * p + 1], ahi[ks], th2, th3);
                mma_bf16(acc[2 * p + 1], ahi[ks], tmp[2], tmp[3]);
                mma_bf16(acc[2 * p + 1], alo[ks], th2, th3);
            }
        }

        if (rep + 1 < MLP_REPS) {
            char* bh = (char*)Bhs[buf ^ 1];
            char* bl = (char*)Bls[buf ^ 1];
#pragma unroll
            for (int q = 0; q < 4; q++) {
                float h0 = fmaxf(pf_p[q].x - pf_a[q].x, 0.f);
                float h1 = fmaxf(pf_p[q].y - pf_a[q].y, 0.f);
                float h2 = fmaxf(pf_p[q].z - pf_a[q].z, 0.f);
                float h3 = fmaxf(pf_p[q].w - pf_a[q].w, 0.f);
                __nv_bfloat162 hiA, hiB, loA, loB;
                hiA.x = __float2bfloat16_rn(h0); hiA.y = __float2bfloat16_rn(h1);
                hiB.x = __float2bfloat16_rn(h2); hiB.y = __float2bfloat16_rn(h3);
                loA.x = __float2bfloat16_rn(h0 - __bfloat162float(hiA.x));
                loA.y = __float2bfloat16_rn(h1 - __bfloat162float(hiA.y));
                loB.x = __float2bfloat16_rn(h2 - __bfloat162float(hiB.x));
                loB.y = __float2bfloat16_rn(h3 - __bfloat162float(hiB.y));
                int k0 = kq * 16 + q * 4;
                int chunk = k0 >> 3;
                int off = col * 128 + ((chunk ^ (col & 7)) << 4) + ((k0 & 7) << 1);
                uint2 vh, vl;
                vh.x = *(unsigned*)&hiA; vh.y = *(unsigned*)&hiB;
                vl.x = *(unsigned*)&loA; vl.y = *(unsigned*)&loB;
                *(uint2*)(bh + off) = vh;
                *(uint2*)(bl + off) = vl;
            }
        }

        int mbase = (blockIdx.x * MLP_REPS + rep) * 2;
        int grp = lane >> 2;
#pragma unroll
        for (int a = 0; a < 2; a++) {
            float m0 = -1e30f, m1 = -1e30f;
#pragma unroll
            for (int nt = a * 4; nt < a * 4 + 4; nt++) {
                m0 = fmaxf(m0, fmaxf(acc[nt][0], acc[nt][1]));
                m1 = fmaxf(m1, fmaxf(acc[nt][2], acc[nt][3]));
            }
            m0 = fmaxf(m0, __shfl_xor_sync(0xffffffffu, m0, 1));
            m0 = fmaxf(m0, __shfl_xor_sync(0xffffffffu, m0, 2));
            m1 = fmaxf(m1, __shfl_xor_sync(0xffffffffu, m1, 1));
            m1 = fmaxf(m1, __shfl_xor_sync(0xffffffffu, m1, 2));
            if ((lane & 3) == 0) {
                float* o = g_hmax + ((size_t)combo * Mn + mbase + a) * 128 + w * 16 + grp;
                o[0] = fmaxf(m0, 0.f);
                o[8] = fmaxf(m1, 0.f);
            }
        }
        __syncthreads();
    }
}

// ---------------------------------------------------------------------------
// K5: wt on tensor cores (unchanged from R8)
// ---------------------------------------------------------------------------
__device__ __forceinline__ void wt_produce(char* bh, char* bl, const float4* pf,
                                           int col, int kq) {
#pragma unroll
    for (int q = 0; q < 4; q++) {
        float4 v = pf[q];
        __nv_bfloat162 hiA, hiB, loA, loB;
        hiA.x = __float2bfloat16_rn(v.x); hiA.y = __float2bfloat16_rn(v.y);
        hiB.x = __float2bfloat16_rn(v.z); hiB.y = __float2bfloat16_rn(v.w);
        loA.x = __float2bfloat16_rn(v.x - __bfloat162float(hiA.x));
        loA.y = __float2bfloat16_rn(v.y - __bfloat162float(hiA.y));
        loB.x = __float2bfloat16_rn(v.z - __bfloat162float(hiB.x));
        loB.y = __float2bfloat16_rn(v.w - __bfloat162float(hiB.y));
        int k0 = kq * 16 + q * 4;
        int chunk = k0 >> 3;
        int off = col * 256 + ((chunk ^ (col & 7)) << 4) + ((k0 & 7) << 1);
        uint2 vh, vl;
        vh.x = *(unsigned*)&hiA; vh.y = *(unsigned*)&hiB;
        vl.x = *(unsigned*)&loA; vl.y = *(unsigned*)&loB;
        *(uint2*)(bh + off) = vh;
        *(uint2*)(bl + off) = vl;
    }
}

__global__ void __launch_bounds__(256) wt_kernel(float* __restrict__ outf) {
    __shared__ __align__(16) __nv_bfloat16 Bh[2][32 * 128];
    __shared__ __align__(16) __nv_bfloat16 Bl[2][32 * 128];

    int t = threadIdx.x;
    int lane = t & 31, w = t >> 5;
    int bs = blockIdx.y;
    int mbase = blockIdx.x * 32;

    int col = t >> 3;
    int kq = t & 7;
    int brow_base = (lane & 7) + ((lane & 16) >> 1);
    int bksel = (lane >> 3) & 1;

    unsigned sBh0 = (unsigned)__cvta_generic_to_shared(Bh[0]);
    unsigned sBl0 = (unsigned)__cvta_generic_to_shared(Bl[0]);

    float4 pf[4];
    {
        const float4* src = (const float4*)(g_hmax +
            (((size_t)(bs * 3 + 0)) * Mn + mbase + col) * 128 + kq * 16);
#pragma unroll
        for (int q = 0; q < 4; q++) pf[q] = src[q];
    }
    wt_produce((char*)Bh[0], (char*)Bl[0], pf, col, kq);
    __syncthreads();

    float tot[2][4][4];
#pragma unroll
    for (int mt = 0; mt < 2; mt++)
#pragma unroll
        for (int nt = 0; nt < 4; nt++)
#pragma unroll
            for (int i = 0; i < 4; i++) tot[mt][nt][i] = 0.f;

    const uint4* fragHi = (const uint4*)g_WtFragHi;
    const uint4* fragLo = (const uint4*)g_WtFragLo;

#pragma unroll
    for (int j = 0; j < 3; j++) {
        if (j < 2) {
            const float4* src = (const float4*)(g_hmax +
                (((size_t)(bs * 3 + j + 1)) * Mn + mbase + col) * 128 + kq * 16);
#pragma unroll
            for (int q = 0; q < 4; q++) pf[q] = src[q];
        }

        float acc[2][4][4];
#pragma unroll
        for (int mt = 0; mt < 2; mt++)
#pragma unroll
            for (int nt = 0; nt < 4; nt++)
#pragma unroll
                for (int i = 0; i < 4; i++) acc[mt][nt][i] = 0.f;

        unsigned sBhj = sBh0 + (j & 1) * 8192;
        unsigned sBlj = sBl0 + (j & 1) * 8192;

#pragma unroll
        for (int ks = 0; ks < 8; ks++) {
            uint4 fh0 = fragHi[((j * 16 + w * 2 + 0) * 8 + ks) * 32 + lane];
            uint4 fl0 = fragLo[((j * 16 + w * 2 + 0) * 8 + ks) * 32 + lane];
            uint4 fh1 = fragHi[((j * 16 + w * 2 + 1) * 8 + ks) * 32 + lane];
            uint4 fl1 = fragLo[((j * 16 + w * 2 + 1) * 8 + ks) * 32 + lane];
            unsigned ah0[4] = {fh0.x, fh0.y, fh0.z, fh0.w};
            unsigned al0[4] = {fl0.x, fl0.y, fl0.z, fl0.w};
            unsigned ah1[4] = {fh1.x, fh1.y, fh1.z, fh1.w};
            unsigned al1[4] = {fl1.x, fl1.y, fl1.z, fl1.w};
            int chunk = ks * 2 + bksel;
#pragma unroll
            for (int p = 0; p < 2; p++) {
                int r = p * 16 + brow_base;
                unsigned off = r * 256 + ((chunk ^ (r & 7)) << 4);
                unsigned hh[4], ll[4];
                ldsm4(hh, sBhj + off);
                ldsm4(ll, sBlj + off);
                mma_bf16(acc[0][2 * p],     ah0, hh[0], hh[1]);
                mma_bf16(acc[0][2 * p],     ah0, ll[0], ll[1]);
                mma_bf16(acc[0][2 * p],     al0, hh[0], hh[1]);
                mma_bf16(acc[0][2 * p + 1], ah0, hh[2], hh[3]);
                mma_bf16(acc[0][2 * p + 1], ah0, ll[2], ll[3]);
                mma_bf16(acc[0][2 * p + 1], al0, hh[2], hh[3]);
                mma_bf16(acc[1][2 * p],     ah1, hh[0], hh[1]);
                mma_bf16(acc[1][2 * p],     ah1, ll[0], ll[1]);
                mma_bf16(acc[1][2 * p],     al1, hh[0], hh[1]);
                mma_bf16(acc[1][2 * p + 1], ah1, hh[2], hh[3]);
                mma_bf16(acc[1][2 * p + 1], ah1, ll[2], ll[3]);
                mma_bf16(acc[1][2 * p + 1], al1, hh[2], hh[3]);
            }
        }

        if (j < 2)
            wt_produce((char*)Bh[(j + 1) & 1], (char*)Bl[(j + 1) & 1], pf, col, kq);

#pragma unroll
        for (int mt = 0; mt < 2; mt++)
#pragma unroll
            for (int nt = 0; nt < 4; nt++)
#pragma unroll
                for (int i = 0; i < 4; i++)
                    tot[mt][nt][i] += fmaxf(acc[mt][nt][i], 0.f);
        __syncthreads();
    }

#pragma unroll
    for (int mt = 0; mt < 2; mt++) {
        int row = w * 32 + mt * 16 + (lane >> 2);
#pragma unroll
        for (int nt = 0; nt < 4; nt++) {
            int c = mbase + nt * 8 + (lane & 3) * 2;
            float2 v0; v0.x = tot[mt][nt][0]; v0.y = tot[mt][nt][1];
            float2 v1; v1.x = tot[mt][nt][2]; v1.y = tot[mt][nt][3];
            *(float2*)&outf[((size_t)bs * 256 + row) * Mn + c] = v0;
            *(float2*)&outf[((size_t)bs * 256 + row + 8) * Mn + c] = v1;
        }
    }
}

// ---------------------------------------------------------------------------
extern "C" void kernel_launch(void* const* d_in, const int* in_sizes, int n_in,
                              void* d_out, int out_size) {
    const float* xyzs = (const float*)d_in[0];
    const float* feats = (const float*)d_in[1];
    const float* Ws0 = (const float*)d_in[2];
    const float* Ws1 = (const float*)d_in[3];
    const float* Wt = (const float*)d_in[4];
    float* out = (float*)d_out;

    const int XYZ_TOTAL = Bn * Sn * Mn * 3;  // 196608

    fps_kernel<<<Bn * Sn, 256>>>(xyzs, out);                         // 1
    wsprep<<<32, 256>>>(Ws1);                                        // 2
    compute_PA<<<768, 256>>>(xyzs, feats, Ws0);                      // 3
    ball_query_kernel<<<dim3(Mn / 8, Bn * Sn * Jn), 256>>>(xyzs);    // 4 (profiled)
    wtfrag_hi<<<192, 256>>>(Wt);                                     // 5
    wtfrag_lo<<<192, 256>>>(Wt);                                     // 6
    mlp_kernel<<<dim3(Mn * Kn / (64 * MLP_REPS), Bn * Sn * Jn), 256>>>();  // 7
    wt_kernel<<<dim3(Mn / 32, Bn * Sn), 256>>>(out + XYZ_TOTAL);     // 8
}